// round 11
// baseline (speedup 1.0000x reference)
#include <cuda_runtime.h>
#include <cuda_fp16.h>
#include <cstdint>

// ---------------- problem constants ----------------
#define B_SZ   2
#define S_LEN  2048
#define D_DIM  2048
#define L_DIM  512
#define NHEADS 16
#define HDIM   128
#define WIN    128
#define SINK   16
#define MROWS  (B_SZ * S_LEN)   // 4096

// ---------------- PTX helpers (base sm_103 ISA only) ----------------
__device__ __forceinline__ uint32_t smem_to_u32(const void* p) {
    uint32_t a;
    asm("{ .reg .u64 t; cvta.to.shared.u64 t, %1; cvt.u32.u64 %0, t; }" : "=r"(a) : "l"(p));
    return a;
}

#define CP_ASYNC16(saddr, gaddr) \
    asm volatile("cp.async.cg.shared.global [%0], [%1], 16;" :: "r"(saddr), "l"(gaddr) : "memory")
#define CP_COMMIT()  asm volatile("cp.async.commit_group;" ::: "memory")
#define CP_WAIT2()   asm volatile("cp.async.wait_group 2;" ::: "memory")
#define CP_WAIT1()   asm volatile("cp.async.wait_group 1;" ::: "memory")
#define CP_WAIT0()   asm volatile("cp.async.wait_group 0;" ::: "memory")

#define LDSM4(r, addr) \
    asm volatile("ldmatrix.sync.aligned.m8n8.x4.shared.b16 {%0,%1,%2,%3}, [%4];" \
        : "=r"((r)[0]), "=r"((r)[1]), "=r"((r)[2]), "=r"((r)[3]) : "r"(addr))
#define LDSM4T(r, addr) \
    asm volatile("ldmatrix.sync.aligned.m8n8.x4.trans.shared.b16 {%0,%1,%2,%3}, [%4];" \
        : "=r"((r)[0]), "=r"((r)[1]), "=r"((r)[2]), "=r"((r)[3]) : "r"(addr))

// fp16 inputs, fp32 accumulate
#define MMA16816(d, a, b0, b1) \
    asm volatile("mma.sync.aligned.m16n8k16.row.col.f32.f16.f16.f32 " \
        "{%0,%1,%2,%3},{%4,%5,%6,%7},{%8,%9},{%0,%1,%2,%3};" \
        : "+f"((d)[0]), "+f"((d)[1]), "+f"((d)[2]), "+f"((d)[3]) \
        : "r"((a)[0]), "r"((a)[1]), "r"((a)[2]), "r"((a)[3]), "r"(b0), "r"(b1))

__device__ __forceinline__ void split2h(float x, float y, uint32_t& hi, uint32_t& lo) {
    __half2 h = __floats2half2_rn(x, y);
    hi = *(uint32_t*)&h;
    __half2 l = __floats2half2_rn(x - __low2float(h), y - __high2float(h));
    lo = *(uint32_t*)&l;
}
__device__ __forceinline__ uint32_t pack2h(float x, float y) {
    __half2 h = __floats2half2_rn(x, y);
    return *(uint32_t*)&h;
}

__device__ __forceinline__ uint32_t sw64(uint32_t off) {
    return off ^ ((off >> 3) & 0x30);
}

// ---------------- scratch (device globals) ----------------
__device__ __align__(256) __half g_Xh  [MROWS * D_DIM];
__device__ __align__(256) __half g_Xl  [MROWS * D_DIM];
__device__ __align__(256) __half g_KV1 [MROWS * L_DIM];   // single fp16
__device__ __align__(256) __half g_Qh  [MROWS * D_DIM];
__device__ __align__(256) __half g_Ql  [MROWS * D_DIM];
__device__ __align__(256) __half g_K1  [MROWS * D_DIM];   // single fp16
__device__ __align__(256) __half g_V1  [MROWS * D_DIM];   // single fp16
__device__ __align__(256) __half g_AO1 [MROWS * D_DIM];   // single fp16
// merged transposed weights (single fp16)
__device__ __align__(256) __half g_W1 [(D_DIM + L_DIM) * D_DIM];
__device__ __align__(256) __half g_W2 [(2 * D_DIM) * L_DIM];
__device__ __align__(256) __half g_WoT[D_DIM * D_DIM];

// ---------------- conversions ----------------
__global__ void split_kernel(const float4* __restrict__ in,
                             uint32_t* __restrict__ hi,
                             uint32_t* __restrict__ lo, int n4)
{
    int i = blockIdx.x * blockDim.x + threadIdx.x;
    if (i >= n4) return;
    float4 v = in[i];
    uint32_t h0, l0, h1, l1;
    split2h(v.x, v.y, h0, l0);
    split2h(v.z, v.w, h1, l1);
    hi[2 * i] = h0; hi[2 * i + 1] = h1;
    lo[2 * i] = l0; lo[2 * i + 1] = l1;
}

// in [K, N] fp32 -> out [N, K] single fp16
__global__ void tsplit_kernel(const float* __restrict__ in,
                              __half* __restrict__ outW,
                              int K, int N)
{
    __shared__ float tile[32][33];
    int kb = blockIdx.y * 32, nb = blockIdx.x * 32;
    int tx = threadIdx.x, ty = threadIdx.y;
#pragma unroll
    for (int j = 0; j < 32; j += 8)
        tile[ty + j][tx] = in[(size_t)(kb + ty + j) * N + nb + tx];
    __syncthreads();
#pragma unroll
    for (int j = 0; j < 32; j += 8) {
        float v = tile[tx][ty + j];
        outW[(size_t)(nb + ty + j) * K + kb + tx] = __float2half_rn(v);
    }
}

// ---------------- fp16 HMMA GEMM (per-tile 1- or 2-pass A side) ----------------
// C[M,N] = A[M,K] @ B^T, B stored [N,K] single fp16.
// two=1: C = Ah*B + Al*B ; two=0: C = Ah*B.  Selected per N-region.
// 128x128 CTA tile, BK=32, 8 warps, 3-stage cp.async, SW64 swizzle, occ 2.
#define MM_STAGE 24576u
#define MM_SMEM_BYTES (3 * 24576)

__device__ __forceinline__ void mm_load_chunk(
    uint32_t sb, int ck, int tid, int two,
    const __half* __restrict__ Ah, const __half* __restrict__ Al,
    const __half* __restrict__ B,
    int m0, int n0, int K)
{
    const int k0 = ck * 32;
#pragma unroll
    for (int it = 0; it < 6; it++) {
        const int arr = it >> 1;                      // 0:Ah 1:Al 2:B
        if (arr == 1 && !two) continue;
        const int u   = ((it & 1) << 8) + tid;        // 0..511
        const int r   = u >> 2;                       // 0..127
        const int cb  = (u & 3) << 4;                 // byte col in 64B row
        const uint32_t sw = sw64((uint32_t)(r * 64 + cb));
        const __half* base = (arr == 0) ? Ah : (arr == 1) ? Al : B;
        const int row0 = (arr < 2) ? m0 : n0;
        const char* g = (const char*)(base + (size_t)(row0 + r) * K + k0) + cb;
        CP_ASYNC16(sb + (uint32_t)arr * 8192u + sw, g);
    }
}

__global__ __launch_bounds__(256, 2)
void mm_kernel(const __half* __restrict__ Ah,
               const __half* __restrict__ Al,
               const __half* __restrict__ B,
               float* __restrict__ C,
               __half* __restrict__ O_a, __half* __restrict__ Ol_a, int ncols_a,
               __half* __restrict__ O_b, int ncols_b,
               int nsplit, int K, int mode_a, int mode_b,
               int two_a, int two_b)
    // mode: 0 = fp32 to C, 1 = fp16 hi/lo split to O_a/Ol_a, 2 = single fp16
{
    extern __shared__ __align__(1024) char dsm[];
    const uint32_t smem = smem_to_u32(dsm);

    const int tid  = threadIdx.x;
    const int wid  = tid >> 5;
    const int lane = tid & 31;
    const int warp_m = wid & 1;
    const int warp_n = wid >> 1;
    const int m0 = blockIdx.y * 128, n0 = blockIdx.x * 128;
    const bool second = (n0 >= nsplit);
    const int two  = second ? two_b : two_a;
    const int mode = second ? mode_b : mode_a;

    float d[4][4][4];
#pragma unroll
    for (int mt = 0; mt < 4; mt++)
#pragma unroll
        for (int nt = 0; nt < 4; nt++)
#pragma unroll
            for (int j = 0; j < 4; j++) d[mt][nt][j] = 0.0f;

    const int nch = K / 32;
    mm_load_chunk(smem,            0, tid, two, Ah, Al, B, m0, n0, K);
    CP_COMMIT();
    mm_load_chunk(smem + MM_STAGE, 1, tid, two, Ah, Al, B, m0, n0, K);
    CP_COMMIT();

    const int a_row  = warp_m * 64 + (lane & 15);
    const int a_kofs = (lane >> 4) << 4;
    const int b_row  = warp_n * 32 + ((lane >> 4) << 3) + (lane & 7);
    const int b_kofs = ((lane >> 3) & 1) << 4;

    for (int i = 0; i < nch; i++) {
        if (i + 2 < nch) {
            mm_load_chunk(smem + (uint32_t)((i + 2) % 3) * MM_STAGE, i + 2, tid, two,
                          Ah, Al, B, m0, n0, K);
            CP_COMMIT();
            CP_WAIT2();
        } else if (i + 1 < nch) {
            CP_WAIT1();
        } else {
            CP_WAIT0();
        }
        __syncthreads();

        const uint32_t sb = smem + (uint32_t)(i % 3) * MM_STAGE;
#pragma unroll
        for (int ks = 0; ks < 2; ks++) {
            const int kb = ks * 32;
            uint32_t bq[2][4];
#pragma unroll
            for (int np = 0; np < 2; np++) {
                const uint32_t sw = sw64((uint32_t)((b_row + np * 16) * 64 + kb + b_kofs));
                LDSM4(bq[np], sb + 16384u + sw);
            }
#pragma unroll
            for (int mt = 0; mt < 4; mt++) {
                uint32_t ah[4], al[4];
                const uint32_t sw = sw64((uint32_t)((a_row + mt * 16) * 64 + kb + a_kofs));
                LDSM4(ah, sb + sw);
                if (two) LDSM4(al, sb + 8192u + sw);
#pragma unroll
                for (int nt = 0; nt < 4; nt++) {
                    const int np = nt >> 1, h = (nt & 1) << 1;
                    MMA16816(d[mt][nt], ah, bq[np][h], bq[np][h + 1]);
                    if (two) MMA16816(d[mt][nt], al, bq[np][h], bq[np][h + 1]);
                }
            }
        }
        __syncthreads();
    }

    // epilogue
    const int gid = lane >> 2, tig = lane & 3;
    const int mbase = m0 + warp_m * 64 + gid;
    if (mode == 0) {
        const int nbase = n0 + warp_n * 32 + tig * 2;
#pragma unroll
        for (int mt = 0; mt < 4; mt++)
#pragma unroll
            for (int nt = 0; nt < 4; nt++) {
                const int m = mbase + mt * 16;
                const int n = nbase + nt * 8;
                *(float2*)(C + (size_t)m * ncols_a + n)       = make_float2(d[mt][nt][0], d[mt][nt][1]);
                *(float2*)(C + (size_t)(m + 8) * ncols_a + n) = make_float2(d[mt][nt][2], d[mt][nt][3]);
            }
    } else {
        __half* oh = second ? O_b : O_a;
        const int nc = second ? ncols_b : ncols_a;
        const int nbase = (second ? n0 - nsplit : n0) + warp_n * 32 + tig * 2;
#pragma unroll
        for (int mt = 0; mt < 4; mt++)
#pragma unroll
            for (int nt = 0; nt < 4; nt++) {
#pragma unroll
                for (int half = 0; half < 2; half++) {
                    const int m = mbase + mt * 16 + half * 8;
                    const int n = nbase + nt * 8;
                    if (mode == 1) {
                        uint32_t hh, ll;
                        split2h(d[mt][nt][half * 2], d[mt][nt][half * 2 + 1], hh, ll);
                        *(uint32_t*)(oh + (size_t)m * nc + n) = hh;
                        *(uint32_t*)(Ol_a + (size_t)m * nc + n) = ll;
                    } else {
                        *(uint32_t*)(oh + (size_t)m * nc + n) =
                            pack2h(d[mt][nt][half * 2], d[mt][nt][half * 2 + 1]);
                    }
                }
            }
    }
}

// ---------------- fp16 flash attention (QK 2-pass, PV 1-pass) ------------------
// Q: fp16 hi/lo split. K,V: single fp16. Output AO: single fp16.
#define AQT 128
#define AKT 64
#define A_STAGE_OFF   65536u           // Qh 32K + Ql 32K
#define A_STAGE_BYTES 32768u           // K 16K + V 16K
#define A_SMEM_BYTES  (65536 + 2 * 32768)

__global__ __launch_bounds__(256, 1) void attn_kernel(
    const __half* __restrict__ Qh_g, const __half* __restrict__ Ql_g,
    const __half* __restrict__ K_g,  const __half* __restrict__ V_g,
    __half* __restrict__ O_g)
{
    extern __shared__ __align__(1024) char dsm[];
    const uint32_t smem = smem_to_u32(dsm);
    const int tid = threadIdx.x, wid = tid >> 5, lane = tid & 31;
    const int b = blockIdx.z, h = blockIdx.y;
    const int q0 = blockIdx.x * AQT;
    const int gid = lane >> 2, tig = lane & 3;
    const int wq = wid * 16;
    const float scale = 0.08838834764831845f;

    {
        const size_t qg = ((size_t)(b * S_LEN + q0)) * D_DIM + h * HDIM;
#pragma unroll
        for (int it = 0; it < 8; it++) {
            int ch = tid + it * 256;
            int row = ch >> 4, dblk = ch & 15;
            uint32_t lrow = (uint32_t)((dblk >> 3) * 128 + row);
            uint32_t off = lrow * 128 + (dblk & 7) * 16;
            uint32_t sw = off ^ ((off >> 3) & 0x70);
            size_t g = qg + (size_t)row * D_DIM + dblk * 8;
            CP_ASYNC16(smem + sw,          (const char*)(Qh_g + g));
            CP_ASYNC16(smem + 32768u + sw, (const char*)(Ql_g + g));
        }
        CP_COMMIT();
    }

    const int ws = q0 - WIN + 1;
    const int tstart = (ws >= 64) ? (ws >> 6) : 1;
    const int tend = (q0 + AQT - 1) >> 6;
    const int cnt = 2 + (tend - tstart);

#define TILE_OF(j) ((j) == 0 ? 0 : (tstart + (j) - 1))
#define LOAD_KV(j) do { \
        int kb_ = TILE_OF(j) * AKT; \
        uint32_t sb_ = smem + A_STAGE_OFF + (uint32_t)((j) & 1) * A_STAGE_BYTES; \
        size_t gb_ = ((size_t)(b * S_LEN + kb_)) * D_DIM + h * HDIM; \
        _Pragma("unroll") \
        for (int it_ = 0; it_ < 4; it_++) { \
            int ch_ = tid + it_ * 256; \
            int row_ = ch_ >> 4, dblk_ = ch_ & 15; \
            uint32_t lrow_ = (uint32_t)((dblk_ >> 3) * 64 + row_); \
            uint32_t off_ = lrow_ * 128 + (dblk_ & 7) * 16; \
            uint32_t sw_ = off_ ^ ((off_ >> 3) & 0x70); \
            size_t g_ = gb_ + (size_t)row_ * D_DIM + dblk_ * 8; \
            CP_ASYNC16(sb_ + sw_,           (const char*)(K_g + g_)); \
            CP_ASYNC16(sb_ + 16384u + sw_,  (const char*)(V_g + g_)); \
        } \
        CP_COMMIT(); \
    } while (0)

    LOAD_KV(0);

    float o[16][4];
#pragma unroll
    for (int dt = 0; dt < 16; dt++)
#pragma unroll
        for (int j = 0; j < 4; j++) o[dt][j] = 0.0f;
    float m0r = -1e30f, m1r = -1e30f, l0r = 0.0f, l1r = 0.0f;

    for (int j = 0; j < cnt; j++) {
        if (j + 1 < cnt) { LOAD_KV(j + 1); CP_WAIT1(); }
        else             { CP_WAIT0(); }
        __syncthreads();

        const uint32_t sb = smem + A_STAGE_OFF + (uint32_t)(j & 1) * A_STAGE_BYTES;
        const int kb = TILE_OF(j) * AKT;

        float s[8][4];
#pragma unroll
        for (int nt = 0; nt < 8; nt++)
#pragma unroll
            for (int jj = 0; jj < 4; jj++) s[nt][jj] = 0.0f;

#pragma unroll
        for (int ks = 0; ks < 8; ks++) {
            uint32_t ah[4], al[4];
            {
                int dd = ks * 16 + ((lane >> 4) << 3);
                int row = wq + (lane & 15);
                uint32_t lrow = (uint32_t)((dd >> 6) * 128 + row);
                uint32_t off = lrow * 128 + (dd & 63) * 2;
                uint32_t sw = off ^ ((off >> 3) & 0x70);
                LDSM4(ah, smem + sw);
                LDSM4(al, smem + 32768u + sw);
            }
#pragma unroll
            for (int np = 0; np < 4; np++) {
                uint32_t bq[4];
                int key = np * 16 + ((lane >> 4) << 3) + (lane & 7);
                int dd = ks * 16 + ((lane >> 3) & 1) * 8;
                uint32_t lrow = (uint32_t)((dd >> 6) * 64 + key);
                uint32_t off = lrow * 128 + (dd & 63) * 2;
                uint32_t sw = off ^ ((off >> 3) & 0x70);
                LDSM4(bq, sb + sw);
#pragma unroll
                for (int tt = 0; tt < 2; tt++) {
                    MMA16816(s[np * 2 + tt], ah, bq[2 * tt], bq[2 * tt + 1]);
                    MMA16816(s[np * 2 + tt], al, bq[2 * tt], bq[2 * tt + 1]);
                }
            }
        }

#pragma unroll
        for (int nt = 0; nt < 8; nt++) {
            const int kc = kb + nt * 8 + tig * 2;
#pragma unroll
            for (int jj = 0; jj < 4; jj++) {
                const int q = q0 + wq + gid + ((jj >> 1) << 3);
                const int k = kc + (jj & 1);
                const bool valid = (k <= q) && ((q - k < WIN) || (k < SINK));
                s[nt][jj] = valid ? s[nt][jj] * scale : -1e30f;
            }
        }

        float tm0 = -1e30f, tm1 = -1e30f;
#pragma unroll
        for (int nt = 0; nt < 8; nt++) {
            tm0 = fmaxf(tm0, fmaxf(s[nt][0], s[nt][1]));
            tm1 = fmaxf(tm1, fmaxf(s[nt][2], s[nt][3]));
        }
        tm0 = fmaxf(tm0, __shfl_xor_sync(0xffffffffu, tm0, 1));
        tm0 = fmaxf(tm0, __shfl_xor_sync(0xffffffffu, tm0, 2));
        tm1 = fmaxf(tm1, __shfl_xor_sync(0xffffffffu, tm1, 1));
        tm1 = fmaxf(tm1, __shfl_xor_sync(0xffffffffu, tm1, 2));
        const float m0n = fmaxf(m0r, tm0), m1n = fmaxf(m1r, tm1);
        const float al0 = __expf(m0r - m0n), al1 = __expf(m1r - m1n);
        m0r = m0n; m1r = m1n;

        float rs0 = 0.0f, rs1 = 0.0f;
#pragma unroll
        for (int nt = 0; nt < 8; nt++) {
            float p0 = __expf(s[nt][0] - m0n);
            float p1 = __expf(s[nt][1] - m0n);
            float p2 = __expf(s[nt][2] - m1n);
            float p3 = __expf(s[nt][3] - m1n);
            s[nt][0] = p0; s[nt][1] = p1; s[nt][2] = p2; s[nt][3] = p3;
            rs0 += p0 + p1; rs1 += p2 + p3;
        }
        rs0 += __shfl_xor_sync(0xffffffffu, rs0, 1);
        rs0 += __shfl_xor_sync(0xffffffffu, rs0, 2);
        rs1 += __shfl_xor_sync(0xffffffffu, rs1, 1);
        rs1 += __shfl_xor_sync(0xffffffffu, rs1, 2);
        l0r = l0r * al0 + rs0;
        l1r = l1r * al1 + rs1;

#pragma unroll
        for (int dt = 0; dt < 16; dt++) {
            o[dt][0] *= al0; o[dt][1] *= al0;
            o[dt][2] *= al1; o[dt][3] *= al1;
        }

        // P -> single fp16 A-fragments (PV 1-pass)
        uint32_t ph[4][4];
#pragma unroll
        for (int ks = 0; ks < 4; ks++) {
            ph[ks][0] = pack2h(s[2 * ks][0],     s[2 * ks][1]);
            ph[ks][1] = pack2h(s[2 * ks][2],     s[2 * ks][3]);
            ph[ks][2] = pack2h(s[2 * ks + 1][0], s[2 * ks + 1][1]);
            ph[ks][3] = pack2h(s[2 * ks + 1][2], s[2 * ks + 1][3]);
        }

#pragma unroll
        for (int np = 0; np < 8; np++) {
#pragma unroll
            for (int ks = 0; ks < 4; ks++) {
                uint32_t vq[4];
                int key = ks * 16 + (lane & 7) + ((lane >> 3) & 1) * 8;
                int dd = np * 16 + ((lane >> 4) << 3);
                uint32_t lrow = (uint32_t)((dd >> 6) * 64 + key);
                uint32_t off = lrow * 128 + (dd & 63) * 2;
                uint32_t sw = off ^ ((off >> 3) & 0x70);
                LDSM4T(vq, sb + 16384u + sw);
#pragma unroll
                for (int tt = 0; tt < 2; tt++)
                    MMA16816(o[np * 2 + tt], ph[ks], vq[2 * tt], vq[2 * tt + 1]);
            }
        }
        __syncthreads();
    }

    const float inv0 = 1.0f / l0r, inv1 = 1.0f / l1r;
    const size_t ob = ((size_t)(b * S_LEN + q0 + wq)) * D_DIM + h * HDIM;
#pragma unroll
    for (int dt = 0; dt < 16; dt++) {
        const int dd = dt * 8 + tig * 2;
        *(uint32_t*)(O_g + ob + (size_t)gid * D_DIM + dd) =
            pack2h(o[dt][0] * inv0, o[dt][1] * inv0);
        *(uint32_t*)(O_g + ob + (size_t)(gid + 8) * D_DIM + dd) =
            pack2h(o[dt][2] * inv1, o[dt][3] * inv1);
    }
}

// ---------------- launch ------------------------------------------------------
extern "C" void kernel_launch(void* const* d_in, const int* in_sizes, int n_in,
                              void* d_out, int out_size)
{
    const float* x   = (const float*)d_in[0];
    const float* Wq  = (const float*)d_in[1];
    const float* Wkv = (const float*)d_in[2];
    const float* Wk  = (const float*)d_in[3];
    const float* Wv  = (const float*)d_in[4];
    const float* Wo  = (const float*)d_in[5];
    float* out = (float*)d_out;

    __half *Xh, *Xl, *KV1, *Qh, *Ql, *K1, *V1, *AO1;
    __half *W1, *W2, *WoT;
    cudaGetSymbolAddress((void**)&Xh, g_Xh);   cudaGetSymbolAddress((void**)&Xl, g_Xl);
    cudaGetSymbolAddress((void**)&KV1, g_KV1);
    cudaGetSymbolAddress((void**)&Qh, g_Qh);   cudaGetSymbolAddress((void**)&Ql, g_Ql);
    cudaGetSymbolAddress((void**)&K1, g_K1);   cudaGetSymbolAddress((void**)&V1, g_V1);
    cudaGetSymbolAddress((void**)&AO1, g_AO1);
    cudaGetSymbolAddress((void**)&W1, g_W1);
    cudaGetSymbolAddress((void**)&W2, g_W2);
    cudaGetSymbolAddress((void**)&WoT, g_WoT);

    cudaFuncSetAttribute(mm_kernel,   cudaFuncAttributeMaxDynamicSharedMemorySize, MM_SMEM_BYTES);
    cudaFuncSetAttribute(attn_kernel, cudaFuncAttributeMaxDynamicSharedMemorySize, A_SMEM_BYTES);

    const dim3 tb(32, 8);
    // --- conversions (single stream, sequential) ---
    {
        int n4 = MROWS * D_DIM / 4;
        split_kernel<<<(n4 + 255) / 256, 256>>>((const float4*)x, (uint32_t*)Xh, (uint32_t*)Xl, n4);
    }
    tsplit_kernel<<<dim3(D_DIM / 32, D_DIM / 32), tb>>>(Wq,  W1, D_DIM, D_DIM);
    tsplit_kernel<<<dim3(L_DIM / 32, D_DIM / 32), tb>>>(Wkv, W1 + (size_t)D_DIM * D_DIM, D_DIM, L_DIM);
    tsplit_kernel<<<dim3(D_DIM / 32, L_DIM / 32), tb>>>(Wk,  W2, L_DIM, D_DIM);
    tsplit_kernel<<<dim3(D_DIM / 32, L_DIM / 32), tb>>>(Wv,  W2 + (size_t)D_DIM * L_DIM, L_DIM, D_DIM);
    tsplit_kernel<<<dim3(D_DIM / 32, D_DIM / 32), tb>>>(Wo,  WoT, D_DIM, D_DIM);

    // --- [Q | KV] = X @ [Wq | Wkv]  (Q: 2-pass split-out; KV: 1-pass single) ---
    mm_kernel<<<dim3((D_DIM + L_DIM) / 128, MROWS / 128), 256, MM_SMEM_BYTES>>>(
        Xh, Xl, W1, nullptr,
        Qh, Ql, D_DIM, KV1, L_DIM, D_DIM, D_DIM, 1, 2, 1, 0);

    // --- [K | V] = KV @ [Wk | Wv]  (1-pass; single fp16 out) ---
    mm_kernel<<<dim3((2 * D_DIM) / 128, MROWS / 128), 256, MM_SMEM_BYTES>>>(
        KV1, nullptr, W2, nullptr,
        K1, nullptr, D_DIM, V1, D_DIM, D_DIM, L_DIM, 2, 2, 0, 0);

    // --- attention (Q split, K/V single, PV 1-pass, AO single out) ---
    attn_kernel<<<dim3(S_LEN / AQT, NHEADS, B_SZ), 256, A_SMEM_BYTES>>>(
        Qh, Ql, K1, V1, AO1);

    // --- out = AO @ Wo (1-pass; fp32 out) ---
    mm_kernel<<<dim3(D_DIM / 128, MROWS / 128), 256, MM_SMEM_BYTES>>>(
        AO1, nullptr, WoT, out,
        nullptr, nullptr, D_DIM, nullptr, 0, 1 << 30, D_DIM, 0, 0, 0, 0);
}

// round 12
// speedup vs baseline: 1.2301x; 1.2301x over previous
#include <cuda_runtime.h>
#include <cuda_fp16.h>
#include <cstdint>

// ---------------- problem constants ----------------
#define B_SZ   2
#define S_LEN  2048
#define D_DIM  2048
#define L_DIM  512
#define NHEADS 16
#define HDIM   128
#define WIN    128
#define SINK   16
#define MROWS  (B_SZ * S_LEN)   // 4096

// ---------------- PTX helpers (base sm_103 ISA only) ----------------
__device__ __forceinline__ uint32_t smem_to_u32(const void* p) {
    uint32_t a;
    asm("{ .reg .u64 t; cvta.to.shared.u64 t, %1; cvt.u32.u64 %0, t; }" : "=r"(a) : "l"(p));
    return a;
}

#define CP_ASYNC16(saddr, gaddr) \
    asm volatile("cp.async.cg.shared.global [%0], [%1], 16;" :: "r"(saddr), "l"(gaddr) : "memory")
#define CP_COMMIT()  asm volatile("cp.async.commit_group;" ::: "memory")
#define CP_WAIT2()   asm volatile("cp.async.wait_group 2;" ::: "memory")
#define CP_WAIT1()   asm volatile("cp.async.wait_group 1;" ::: "memory")
#define CP_WAIT0()   asm volatile("cp.async.wait_group 0;" ::: "memory")

#define LDSM4(r, addr) \
    asm volatile("ldmatrix.sync.aligned.m8n8.x4.shared.b16 {%0,%1,%2,%3}, [%4];" \
        : "=r"((r)[0]), "=r"((r)[1]), "=r"((r)[2]), "=r"((r)[3]) : "r"(addr))
#define LDSM4T(r, addr) \
    asm volatile("ldmatrix.sync.aligned.m8n8.x4.trans.shared.b16 {%0,%1,%2,%3}, [%4];" \
        : "=r"((r)[0]), "=r"((r)[1]), "=r"((r)[2]), "=r"((r)[3]) : "r"(addr))

// fp16 inputs, fp32 accumulate
#define MMA16816(d, a, b0, b1) \
    asm volatile("mma.sync.aligned.m16n8k16.row.col.f32.f16.f16.f32 " \
        "{%0,%1,%2,%3},{%4,%5,%6,%7},{%8,%9},{%0,%1,%2,%3};" \
        : "+f"((d)[0]), "+f"((d)[1]), "+f"((d)[2]), "+f"((d)[3]) \
        : "r"((a)[0]), "r"((a)[1]), "r"((a)[2]), "r"((a)[3]), "r"(b0), "r"(b1))

__device__ __forceinline__ void split2h(float x, float y, uint32_t& hi, uint32_t& lo) {
    __half2 h = __floats2half2_rn(x, y);
    hi = *(uint32_t*)&h;
    __half2 l = __floats2half2_rn(x - __low2float(h), y - __high2float(h));
    lo = *(uint32_t*)&l;
}
__device__ __forceinline__ uint32_t pack2h(float x, float y) {
    __half2 h = __floats2half2_rn(x, y);
    return *(uint32_t*)&h;
}

__device__ __forceinline__ uint32_t sw64(uint32_t off) {
    return off ^ ((off >> 3) & 0x30);
}

// ---------------- scratch (device globals) ----------------
__device__ __align__(256) __half g_Xh  [MROWS * D_DIM];
__device__ __align__(256) __half g_Xl  [MROWS * D_DIM];
__device__ __align__(256) __half g_KV1 [MROWS * L_DIM];   // single fp16
__device__ __align__(256) __half g_Qh  [MROWS * D_DIM];
__device__ __align__(256) __half g_Ql  [MROWS * D_DIM];
__device__ __align__(256) __half g_K1  [MROWS * D_DIM];   // single fp16
__device__ __align__(256) __half g_V1  [MROWS * D_DIM];   // single fp16
__device__ __align__(256) __half g_AO1 [MROWS * D_DIM];   // single fp16
// merged transposed weights (single fp16)
__device__ __align__(256) __half g_W1 [(D_DIM + L_DIM) * D_DIM];
__device__ __align__(256) __half g_W2 [(2 * D_DIM) * L_DIM];
__device__ __align__(256) __half g_WoT[D_DIM * D_DIM];

// ---------------- conversions ----------------
__global__ void split_kernel(const float4* __restrict__ in,
                             uint32_t* __restrict__ hi,
                             uint32_t* __restrict__ lo, int n4)
{
    int i = blockIdx.x * blockDim.x + threadIdx.x;
    if (i >= n4) return;
    float4 v = in[i];
    uint32_t h0, l0, h1, l1;
    split2h(v.x, v.y, h0, l0);
    split2h(v.z, v.w, h1, l1);
    hi[2 * i] = h0; hi[2 * i + 1] = h1;
    lo[2 * i] = l0; lo[2 * i + 1] = l1;
}

// in [K, N] fp32 -> out [N, K] single fp16
__global__ void tsplit_kernel(const float* __restrict__ in,
                              __half* __restrict__ outW,
                              int K, int N)
{
    __shared__ float tile[32][33];
    int kb = blockIdx.y * 32, nb = blockIdx.x * 32;
    int tx = threadIdx.x, ty = threadIdx.y;
#pragma unroll
    for (int j = 0; j < 32; j += 8)
        tile[ty + j][tx] = in[(size_t)(kb + ty + j) * N + nb + tx];
    __syncthreads();
#pragma unroll
    for (int j = 0; j < 32; j += 8) {
        float v = tile[tx][ty + j];
        outW[(size_t)(nb + ty + j) * K + kb + tx] = __float2half_rn(v);
    }
}

// ---------------- fp16 HMMA GEMM (compile-time 1-/2-pass body) -----------------
// C[M,N] = A[M,K] @ B^T, B stored [N,K] single fp16.
// TWO=1: C = Ah*B + Al*B ; TWO=0: C = Ah*B.
// 128x128 CTA tile, BK=32, 8 warps, 3-stage cp.async, SW64 swizzle, occ 2.
#define MM_STAGE 24576u
#define MM_SMEM_BYTES (3 * 24576)

template<int TWO>
__device__ __forceinline__ void mm_load_chunk(
    uint32_t sb, int ck, int tid,
    const __half* __restrict__ Ah, const __half* __restrict__ Al,
    const __half* __restrict__ B,
    int m0, int n0, int K)
{
    const int k0 = ck * 32;
#pragma unroll
    for (int it = 0; it < 6; it++) {
        const int arr = it >> 1;                      // 0:Ah 1:Al 2:B
        if (arr == 1 && !TWO) continue;
        const int u   = ((it & 1) << 8) + tid;        // 0..511
        const int r   = u >> 2;                       // 0..127
        const int cb  = (u & 3) << 4;                 // byte col in 64B row
        const uint32_t sw = sw64((uint32_t)(r * 64 + cb));
        const __half* base = (arr == 0) ? Ah : (arr == 1) ? Al : B;
        const int row0 = (arr < 2) ? m0 : n0;
        const char* g = (const char*)(base + (size_t)(row0 + r) * K + k0) + cb;
        CP_ASYNC16(sb + (uint32_t)arr * 8192u + sw, g);
    }
}

// Full mainloop + epilogue, specialized at compile time on TWO.
template<int TWO>
__device__ __forceinline__ void mm_body(
    uint32_t smem, int tid,
    const __half* __restrict__ Ah, const __half* __restrict__ Al,
    const __half* __restrict__ B,
    float* __restrict__ C,
    __half* __restrict__ Oh, __half* __restrict__ Ol,
    int m0, int n0, int nout0, int ncols, int K, int mode)
    // mode: 0 = fp32 to C, 1 = fp16 hi/lo split to Oh/Ol, 2 = single fp16 to Oh
{
    const int wid  = tid >> 5;
    const int lane = tid & 31;
    const int warp_m = wid & 1;
    const int warp_n = wid >> 1;

    float d[4][4][4];
#pragma unroll
    for (int mt = 0; mt < 4; mt++)
#pragma unroll
        for (int nt = 0; nt < 4; nt++)
#pragma unroll
            for (int j = 0; j < 4; j++) d[mt][nt][j] = 0.0f;

    const int nch = K / 32;
    mm_load_chunk<TWO>(smem,            0, tid, Ah, Al, B, m0, n0, K);
    CP_COMMIT();
    mm_load_chunk<TWO>(smem + MM_STAGE, 1, tid, Ah, Al, B, m0, n0, K);
    CP_COMMIT();

    const int a_row  = warp_m * 64 + (lane & 15);
    const int a_kofs = (lane >> 4) << 4;
    const int b_row  = warp_n * 32 + ((lane >> 4) << 3) + (lane & 7);
    const int b_kofs = ((lane >> 3) & 1) << 4;

    for (int i = 0; i < nch; i++) {
        if (i + 2 < nch) {
            mm_load_chunk<TWO>(smem + (uint32_t)((i + 2) % 3) * MM_STAGE, i + 2, tid,
                               Ah, Al, B, m0, n0, K);
            CP_COMMIT();
            CP_WAIT2();
        } else if (i + 1 < nch) {
            CP_WAIT1();
        } else {
            CP_WAIT0();
        }
        __syncthreads();

        const uint32_t sb = smem + (uint32_t)(i % 3) * MM_STAGE;
#pragma unroll
        for (int ks = 0; ks < 2; ks++) {
            const int kb = ks * 32;
            uint32_t bq[2][4];
#pragma unroll
            for (int np = 0; np < 2; np++) {
                const uint32_t sw = sw64((uint32_t)((b_row + np * 16) * 64 + kb + b_kofs));
                LDSM4(bq[np], sb + 16384u + sw);
            }
#pragma unroll
            for (int mt = 0; mt < 4; mt++) {
                uint32_t ah[4], al[4];
                const uint32_t sw = sw64((uint32_t)((a_row + mt * 16) * 64 + kb + a_kofs));
                LDSM4(ah, sb + sw);
                if (TWO) LDSM4(al, sb + 8192u + sw);
#pragma unroll
                for (int nt = 0; nt < 4; nt++) {
                    const int np = nt >> 1, h = (nt & 1) << 1;
                    MMA16816(d[mt][nt], ah, bq[np][h], bq[np][h + 1]);
                    if (TWO) MMA16816(d[mt][nt], al, bq[np][h], bq[np][h + 1]);
                }
            }
        }
        __syncthreads();
    }

    // epilogue
    const int gid = lane >> 2, tig = lane & 3;
    const int mbase = m0 + warp_m * 64 + gid;
    if (mode == 0) {
        const int nbase = nout0 + warp_n * 32 + tig * 2;
#pragma unroll
        for (int mt = 0; mt < 4; mt++)
#pragma unroll
            for (int nt = 0; nt < 4; nt++) {
                const int m = mbase + mt * 16;
                const int n = nbase + nt * 8;
                *(float2*)(C + (size_t)m * ncols + n)       = make_float2(d[mt][nt][0], d[mt][nt][1]);
                *(float2*)(C + (size_t)(m + 8) * ncols + n) = make_float2(d[mt][nt][2], d[mt][nt][3]);
            }
    } else {
        const int nbase = nout0 + warp_n * 32 + tig * 2;
#pragma unroll
        for (int mt = 0; mt < 4; mt++)
#pragma unroll
            for (int nt = 0; nt < 4; nt++) {
#pragma unroll
                for (int half = 0; half < 2; half++) {
                    const int m = mbase + mt * 16 + half * 8;
                    const int n = nbase + nt * 8;
                    if (mode == 1) {
                        uint32_t hh, ll;
                        split2h(d[mt][nt][half * 2], d[mt][nt][half * 2 + 1], hh, ll);
                        *(uint32_t*)(Oh + (size_t)m * ncols + n) = hh;
                        *(uint32_t*)(Ol + (size_t)m * ncols + n) = ll;
                    } else {
                        *(uint32_t*)(Oh + (size_t)m * ncols + n) =
                            pack2h(d[mt][nt][half * 2], d[mt][nt][half * 2 + 1]);
                    }
                }
            }
    }
}

template<int TWO_A, int TWO_B>
__global__ __launch_bounds__(256, 2)
void mm_kernel(const __half* __restrict__ Ah,
               const __half* __restrict__ Al,
               const __half* __restrict__ B,
               float* __restrict__ C,
               __half* __restrict__ O_a, __half* __restrict__ Ol_a, int ncols_a,
               __half* __restrict__ O_b, int ncols_b,
               int nsplit, int K, int mode_a, int mode_b)
{
    extern __shared__ __align__(1024) char dsm[];
    const uint32_t smem = smem_to_u32(dsm);
    const int tid = threadIdx.x;
    const int m0 = blockIdx.y * 128, n0 = blockIdx.x * 128;
    const bool second = (n0 >= nsplit);

    if (!second) {
        mm_body<TWO_A>(smem, tid, Ah, Al, B, C, O_a, Ol_a,
                       m0, n0, n0, ncols_a, K, mode_a);
    } else {
        mm_body<TWO_B>(smem, tid, Ah, Al, B, C, O_b, nullptr,
                       m0, n0, n0 - nsplit, ncols_b, K, mode_b);
    }
}

// ---------------- fp16 flash attention (QK 2-pass, PV 1-pass) ------------------
// Q: fp16 hi/lo split. K,V: single fp16. Output AO: single fp16.
#define AQT 128
#define AKT 64
#define A_STAGE_OFF   65536u           // Qh 32K + Ql 32K
#define A_STAGE_BYTES 32768u           // K 16K + V 16K
#define A_SMEM_BYTES  (65536 + 2 * 32768)

__global__ __launch_bounds__(256, 1) void attn_kernel(
    const __half* __restrict__ Qh_g, const __half* __restrict__ Ql_g,
    const __half* __restrict__ K_g,  const __half* __restrict__ V_g,
    __half* __restrict__ O_g)
{
    extern __shared__ __align__(1024) char dsm[];
    const uint32_t smem = smem_to_u32(dsm);
    const int tid = threadIdx.x, wid = tid >> 5, lane = tid & 31;
    const int b = blockIdx.z, h = blockIdx.y;
    const int q0 = blockIdx.x * AQT;
    const int gid = lane >> 2, tig = lane & 3;
    const int wq = wid * 16;
    const float scale = 0.08838834764831845f;

    {
        const size_t qg = ((size_t)(b * S_LEN + q0)) * D_DIM + h * HDIM;
#pragma unroll
        for (int it = 0; it < 8; it++) {
            int ch = tid + it * 256;
            int row = ch >> 4, dblk = ch & 15;
            uint32_t lrow = (uint32_t)((dblk >> 3) * 128 + row);
            uint32_t off = lrow * 128 + (dblk & 7) * 16;
            uint32_t sw = off ^ ((off >> 3) & 0x70);
            size_t g = qg + (size_t)row * D_DIM + dblk * 8;
            CP_ASYNC16(smem + sw,          (const char*)(Qh_g + g));
            CP_ASYNC16(smem + 32768u + sw, (const char*)(Ql_g + g));
        }
        CP_COMMIT();
    }

    const int ws = q0 - WIN + 1;
    const int tstart = (ws >= 64) ? (ws >> 6) : 1;
    const int tend = (q0 + AQT - 1) >> 6;
    const int cnt = 2 + (tend - tstart);

#define TILE_OF(j) ((j) == 0 ? 0 : (tstart + (j) - 1))
#define LOAD_KV(j) do { \
        int kb_ = TILE_OF(j) * AKT; \
        uint32_t sb_ = smem + A_STAGE_OFF + (uint32_t)((j) & 1) * A_STAGE_BYTES; \
        size_t gb_ = ((size_t)(b * S_LEN + kb_)) * D_DIM + h * HDIM; \
        _Pragma("unroll") \
        for (int it_ = 0; it_ < 4; it_++) { \
            int ch_ = tid + it_ * 256; \
            int row_ = ch_ >> 4, dblk_ = ch_ & 15; \
            uint32_t lrow_ = (uint32_t)((dblk_ >> 3) * 64 + row_); \
            uint32_t off_ = lrow_ * 128 + (dblk_ & 7) * 16; \
            uint32_t sw_ = off_ ^ ((off_ >> 3) & 0x70); \
            size_t g_ = gb_ + (size_t)row_ * D_DIM + dblk_ * 8; \
            CP_ASYNC16(sb_ + sw_,           (const char*)(K_g + g_)); \
            CP_ASYNC16(sb_ + 16384u + sw_,  (const char*)(V_g + g_)); \
        } \
        CP_COMMIT(); \
    } while (0)

    LOAD_KV(0);

    float o[16][4];
#pragma unroll
    for (int dt = 0; dt < 16; dt++)
#pragma unroll
        for (int j = 0; j < 4; j++) o[dt][j] = 0.0f;
    float m0r = -1e30f, m1r = -1e30f, l0r = 0.0f, l1r = 0.0f;

    for (int j = 0; j < cnt; j++) {
        if (j + 1 < cnt) { LOAD_KV(j + 1); CP_WAIT1(); }
        else             { CP_WAIT0(); }
        __syncthreads();

        const uint32_t sb = smem + A_STAGE_OFF + (uint32_t)(j & 1) * A_STAGE_BYTES;
        const int kb = TILE_OF(j) * AKT;

        float s[8][4];
#pragma unroll
        for (int nt = 0; nt < 8; nt++)
#pragma unroll
            for (int jj = 0; jj < 4; jj++) s[nt][jj] = 0.0f;

#pragma unroll
        for (int ks = 0; ks < 8; ks++) {
            uint32_t ah[4], al[4];
            {
                int dd = ks * 16 + ((lane >> 4) << 3);
                int row = wq + (lane & 15);
                uint32_t lrow = (uint32_t)((dd >> 6) * 128 + row);
                uint32_t off = lrow * 128 + (dd & 63) * 2;
                uint32_t sw = off ^ ((off >> 3) & 0x70);
                LDSM4(ah, smem + sw);
                LDSM4(al, smem + 32768u + sw);
            }
#pragma unroll
            for (int np = 0; np < 4; np++) {
                uint32_t bq[4];
                int key = np * 16 + ((lane >> 4) << 3) + (lane & 7);
                int dd = ks * 16 + ((lane >> 3) & 1) * 8;
                uint32_t lrow = (uint32_t)((dd >> 6) * 64 + key);
                uint32_t off = lrow * 128 + (dd & 63) * 2;
                uint32_t sw = off ^ ((off >> 3) & 0x70);
                LDSM4(bq, sb + sw);
#pragma unroll
                for (int tt = 0; tt < 2; tt++) {
                    MMA16816(s[np * 2 + tt], ah, bq[2 * tt], bq[2 * tt + 1]);
                    MMA16816(s[np * 2 + tt], al, bq[2 * tt], bq[2 * tt + 1]);
                }
            }
        }

#pragma unroll
        for (int nt = 0; nt < 8; nt++) {
            const int kc = kb + nt * 8 + tig * 2;
#pragma unroll
            for (int jj = 0; jj < 4; jj++) {
                const int q = q0 + wq + gid + ((jj >> 1) << 3);
                const int k = kc + (jj & 1);
                const bool valid = (k <= q) && ((q - k < WIN) || (k < SINK));
                s[nt][jj] = valid ? s[nt][jj] * scale : -1e30f;
            }
        }

        float tm0 = -1e30f, tm1 = -1e30f;
#pragma unroll
        for (int nt = 0; nt < 8; nt++) {
            tm0 = fmaxf(tm0, fmaxf(s[nt][0], s[nt][1]));
            tm1 = fmaxf(tm1, fmaxf(s[nt][2], s[nt][3]));
        }
        tm0 = fmaxf(tm0, __shfl_xor_sync(0xffffffffu, tm0, 1));
        tm0 = fmaxf(tm0, __shfl_xor_sync(0xffffffffu, tm0, 2));
        tm1 = fmaxf(tm1, __shfl_xor_sync(0xffffffffu, tm1, 1));
        tm1 = fmaxf(tm1, __shfl_xor_sync(0xffffffffu, tm1, 2));
        const float m0n = fmaxf(m0r, tm0), m1n = fmaxf(m1r, tm1);
        const float al0 = __expf(m0r - m0n), al1 = __expf(m1r - m1n);
        m0r = m0n; m1r = m1n;

        float rs0 = 0.0f, rs1 = 0.0f;
#pragma unroll
        for (int nt = 0; nt < 8; nt++) {
            float p0 = __expf(s[nt][0] - m0n);
            float p1 = __expf(s[nt][1] - m0n);
            float p2 = __expf(s[nt][2] - m1n);
            float p3 = __expf(s[nt][3] - m1n);
            s[nt][0] = p0; s[nt][1] = p1; s[nt][2] = p2; s[nt][3] = p3;
            rs0 += p0 + p1; rs1 += p2 + p3;
        }
        rs0 += __shfl_xor_sync(0xffffffffu, rs0, 1);
        rs0 += __shfl_xor_sync(0xffffffffu, rs0, 2);
        rs1 += __shfl_xor_sync(0xffffffffu, rs1, 1);
        rs1 += __shfl_xor_sync(0xffffffffu, rs1, 2);
        l0r = l0r * al0 + rs0;
        l1r = l1r * al1 + rs1;

#pragma unroll
        for (int dt = 0; dt < 16; dt++) {
            o[dt][0] *= al0; o[dt][1] *= al0;
            o[dt][2] *= al1; o[dt][3] *= al1;
        }

        // P -> single fp16 A-fragments (PV 1-pass)
        uint32_t ph[4][4];
#pragma unroll
        for (int ks = 0; ks < 4; ks++) {
            ph[ks][0] = pack2h(s[2 * ks][0],     s[2 * ks][1]);
            ph[ks][1] = pack2h(s[2 * ks][2],     s[2 * ks][3]);
            ph[ks][2] = pack2h(s[2 * ks + 1][0], s[2 * ks + 1][1]);
            ph[ks][3] = pack2h(s[2 * ks + 1][2], s[2 * ks + 1][3]);
        }

#pragma unroll
        for (int np = 0; np < 8; np++) {
#pragma unroll
            for (int ks = 0; ks < 4; ks++) {
                uint32_t vq[4];
                int key = ks * 16 + (lane & 7) + ((lane >> 3) & 1) * 8;
                int dd = np * 16 + ((lane >> 4) << 3);
                uint32_t lrow = (uint32_t)((dd >> 6) * 64 + key);
                uint32_t off = lrow * 128 + (dd & 63) * 2;
                uint32_t sw = off ^ ((off >> 3) & 0x70);
                LDSM4T(vq, sb + 16384u + sw);
#pragma unroll
                for (int tt = 0; tt < 2; tt++)
                    MMA16816(o[np * 2 + tt], ph[ks], vq[2 * tt], vq[2 * tt + 1]);
            }
        }
        __syncthreads();
    }

    const float inv0 = 1.0f / l0r, inv1 = 1.0f / l1r;
    const size_t ob = ((size_t)(b * S_LEN + q0 + wq)) * D_DIM + h * HDIM;
#pragma unroll
    for (int dt = 0; dt < 16; dt++) {
        const int dd = dt * 8 + tig * 2;
        *(uint32_t*)(O_g + ob + (size_t)gid * D_DIM + dd) =
            pack2h(o[dt][0] * inv0, o[dt][1] * inv0);
        *(uint32_t*)(O_g + ob + (size_t)(gid + 8) * D_DIM + dd) =
            pack2h(o[dt][2] * inv1, o[dt][3] * inv1);
    }
}

// ---------------- launch ------------------------------------------------------
extern "C" void kernel_launch(void* const* d_in, const int* in_sizes, int n_in,
                              void* d_out, int out_size)
{
    const float* x   = (const float*)d_in[0];
    const float* Wq  = (const float*)d_in[1];
    const float* Wkv = (const float*)d_in[2];
    const float* Wk  = (const float*)d_in[3];
    const float* Wv  = (const float*)d_in[4];
    const float* Wo  = (const float*)d_in[5];
    float* out = (float*)d_out;

    __half *Xh, *Xl, *KV1, *Qh, *Ql, *K1, *V1, *AO1;
    __half *W1, *W2, *WoT;
    cudaGetSymbolAddress((void**)&Xh, g_Xh);   cudaGetSymbolAddress((void**)&Xl, g_Xl);
    cudaGetSymbolAddress((void**)&KV1, g_KV1);
    cudaGetSymbolAddress((void**)&Qh, g_Qh);   cudaGetSymbolAddress((void**)&Ql, g_Ql);
    cudaGetSymbolAddress((void**)&K1, g_K1);   cudaGetSymbolAddress((void**)&V1, g_V1);
    cudaGetSymbolAddress((void**)&AO1, g_AO1);
    cudaGetSymbolAddress((void**)&W1, g_W1);
    cudaGetSymbolAddress((void**)&W2, g_W2);
    cudaGetSymbolAddress((void**)&WoT, g_WoT);

    cudaFuncSetAttribute(mm_kernel<1,0>, cudaFuncAttributeMaxDynamicSharedMemorySize, MM_SMEM_BYTES);
    cudaFuncSetAttribute(mm_kernel<0,0>, cudaFuncAttributeMaxDynamicSharedMemorySize, MM_SMEM_BYTES);
    cudaFuncSetAttribute(attn_kernel,    cudaFuncAttributeMaxDynamicSharedMemorySize, A_SMEM_BYTES);

    const dim3 tb(32, 8);
    // --- conversions (single stream, sequential) ---
    {
        int n4 = MROWS * D_DIM / 4;
        split_kernel<<<(n4 + 255) / 256, 256>>>((const float4*)x, (uint32_t*)Xh, (uint32_t*)Xl, n4);
    }
    tsplit_kernel<<<dim3(D_DIM / 32, D_DIM / 32), tb>>>(Wq,  W1, D_DIM, D_DIM);
    tsplit_kernel<<<dim3(L_DIM / 32, D_DIM / 32), tb>>>(Wkv, W1 + (size_t)D_DIM * D_DIM, D_DIM, L_DIM);
    tsplit_kernel<<<dim3(D_DIM / 32, L_DIM / 32), tb>>>(Wk,  W2, L_DIM, D_DIM);
    tsplit_kernel<<<dim3(D_DIM / 32, L_DIM / 32), tb>>>(Wv,  W2 + (size_t)D_DIM * L_DIM, L_DIM, D_DIM);
    tsplit_kernel<<<dim3(D_DIM / 32, D_DIM / 32), tb>>>(Wo,  WoT, D_DIM, D_DIM);

    // --- [Q | KV] = X @ [Wq | Wkv]  (Q: 2-pass split-out; KV: 1-pass single) ---
    mm_kernel<1,0><<<dim3((D_DIM + L_DIM) / 128, MROWS / 128), 256, MM_SMEM_BYTES>>>(
        Xh, Xl, W1, nullptr,
        Qh, Ql, D_DIM, KV1, L_DIM, D_DIM, D_DIM, 1, 2);

    // --- [K | V] = KV @ [Wk | Wv]  (1-pass; single fp16 out) ---
    mm_kernel<0,0><<<dim3((2 * D_DIM) / 128, MROWS / 128), 256, MM_SMEM_BYTES>>>(
        KV1, nullptr, W2, nullptr,
        K1, nullptr, D_DIM, V1, D_DIM, D_DIM, L_DIM, 2, 2);

    // --- attention (Q split, K/V single, PV 1-pass, AO single out) ---
    attn_kernel<<<dim3(S_LEN / AQT, NHEADS, B_SZ), 256, A_SMEM_BYTES>>>(
        Qh, Ql, K1, V1, AO1);

    // --- out = AO @ Wo (1-pass; fp32 out) ---
    mm_kernel<0,0><<<dim3(D_DIM / 128, MROWS / 128), 256, MM_SMEM_BYTES>>>(
        AO1, nullptr, WoT, out,
        nullptr, nullptr, D_DIM, nullptr, 0, 1 << 30, D_DIM, 0, 0);
}

// round 13
// speedup vs baseline: 1.5413x; 1.2529x over previous
#include <cuda_runtime.h>
#include <cuda_fp16.h>
#include <cstdint>

// ---------------- problem constants ----------------
#define B_SZ   2
#define S_LEN  2048
#define D_DIM  2048
#define L_DIM  512
#define NHEADS 16
#define HDIM   128
#define WIN    128
#define SINK   16
#define MROWS  (B_SZ * S_LEN)   // 4096

// ---------------- PTX helpers (base sm_103 ISA only) ----------------
__device__ __forceinline__ uint32_t smem_to_u32(const void* p) {
    uint32_t a;
    asm("{ .reg .u64 t; cvta.to.shared.u64 t, %1; cvt.u32.u64 %0, t; }" : "=r"(a) : "l"(p));
    return a;
}

#define CP_ASYNC16(saddr, gaddr) \
    asm volatile("cp.async.cg.shared.global [%0], [%1], 16;" :: "r"(saddr), "l"(gaddr) : "memory")
#define CP_COMMIT()  asm volatile("cp.async.commit_group;" ::: "memory")
#define CP_WAIT2()   asm volatile("cp.async.wait_group 2;" ::: "memory")
#define CP_WAIT1()   asm volatile("cp.async.wait_group 1;" ::: "memory")
#define CP_WAIT0()   asm volatile("cp.async.wait_group 0;" ::: "memory")

#define LDSM4(r, addr) \
    asm volatile("ldmatrix.sync.aligned.m8n8.x4.shared.b16 {%0,%1,%2,%3}, [%4];" \
        : "=r"((r)[0]), "=r"((r)[1]), "=r"((r)[2]), "=r"((r)[3]) : "r"(addr))
#define LDSM4T(r, addr) \
    asm volatile("ldmatrix.sync.aligned.m8n8.x4.trans.shared.b16 {%0,%1,%2,%3}, [%4];" \
        : "=r"((r)[0]), "=r"((r)[1]), "=r"((r)[2]), "=r"((r)[3]) : "r"(addr))

// fp16 inputs, fp32 accumulate
#define MMA16816(d, a, b0, b1) \
    asm volatile("mma.sync.aligned.m16n8k16.row.col.f32.f16.f16.f32 " \
        "{%0,%1,%2,%3},{%4,%5,%6,%7},{%8,%9},{%0,%1,%2,%3};" \
        : "+f"((d)[0]), "+f"((d)[1]), "+f"((d)[2]), "+f"((d)[3]) \
        : "r"((a)[0]), "r"((a)[1]), "r"((a)[2]), "r"((a)[3]), "r"(b0), "r"(b1))

__device__ __forceinline__ uint32_t pack2h(float x, float y) {
    __half2 h = __floats2half2_rn(x, y);
    return *(uint32_t*)&h;
}

__device__ __forceinline__ uint32_t sw64(uint32_t off) {
    return off ^ ((off >> 3) & 0x30);
}

// ---------------- scratch (device globals; all single fp16 now) ---------------
__device__ __align__(256) __half g_X1  [MROWS * D_DIM];
__device__ __align__(256) __half g_KV1 [MROWS * L_DIM];
__device__ __align__(256) __half g_Q1  [MROWS * D_DIM];
__device__ __align__(256) __half g_K1  [MROWS * D_DIM];
__device__ __align__(256) __half g_V1  [MROWS * D_DIM];
__device__ __align__(256) __half g_AO1 [MROWS * D_DIM];
// merged transposed weights (single fp16)
__device__ __align__(256) __half g_W1 [(D_DIM + L_DIM) * D_DIM];
__device__ __align__(256) __half g_W2 [(2 * D_DIM) * L_DIM];
__device__ __align__(256) __half g_WoT[D_DIM * D_DIM];

// ---------------- conversions ----------------
__global__ void convert_kernel(const float4* __restrict__ in,
                               uint32_t* __restrict__ out, int n4)
{
    int i = blockIdx.x * blockDim.x + threadIdx.x;
    if (i >= n4) return;
    float4 v = in[i];
    out[2 * i]     = pack2h(v.x, v.y);
    out[2 * i + 1] = pack2h(v.z, v.w);
}

// in [K, N] fp32 -> out [N, K] single fp16
__global__ void tsplit_kernel(const float* __restrict__ in,
                              __half* __restrict__ outW,
                              int K, int N)
{
    __shared__ float tile[32][33];
    int kb = blockIdx.y * 32, nb = blockIdx.x * 32;
    int tx = threadIdx.x, ty = threadIdx.y;
#pragma unroll
    for (int j = 0; j < 32; j += 8)
        tile[ty + j][tx] = in[(size_t)(kb + ty + j) * N + nb + tx];
    __syncthreads();
#pragma unroll
    for (int j = 0; j < 32; j += 8) {
        float v = tile[tx][ty + j];
        outW[(size_t)(nb + ty + j) * K + kb + tx] = __float2half_rn(v);
    }
}

// ---------------- fp16 1-pass HMMA GEMM ---------------------------------------
// C[M,N] = A[M,K] @ B^T, B stored [N,K] single fp16. fp32 accumulate.
// 128x128 CTA tile, BK=32, 8 warps, 3-stage cp.async, SW64 swizzle, occ 2.
// Stage: A 8K | B 8K = 16KB; 3 stages = 48KB.
#define MM_STAGE 16384u
#define MM_SMEM_BYTES (3 * 16384)

__device__ __forceinline__ void mm_load_chunk(
    uint32_t sb, int ck, int tid,
    const __half* __restrict__ A, const __half* __restrict__ B,
    int m0, int n0, int K)
{
    const int k0 = ck * 32;
#pragma unroll
    for (int it = 0; it < 4; it++) {
        const int arr = it >> 1;                      // 0:A 1:B
        const int u   = ((it & 1) << 8) + tid;        // 0..511
        const int r   = u >> 2;                       // 0..127
        const int cb  = (u & 3) << 4;                 // byte col in 64B row
        const uint32_t sw = sw64((uint32_t)(r * 64 + cb));
        const __half* base = (arr == 0) ? A : B;
        const int row0 = (arr == 0) ? m0 : n0;
        const char* g = (const char*)(base + (size_t)(row0 + r) * K + k0) + cb;
        CP_ASYNC16(sb + (uint32_t)arr * 8192u + sw, g);
    }
}

// Full mainloop + epilogue.
__device__ __forceinline__ void mm_body(
    uint32_t smem, int tid,
    const __half* __restrict__ A, const __half* __restrict__ B,
    float* __restrict__ C, __half* __restrict__ Oh,
    int m0, int n0, int nout0, int ncols, int K, int mode)
    // mode: 0 = fp32 to C, 2 = single fp16 to Oh
{
    const int wid  = tid >> 5;
    const int lane = tid & 31;
    const int warp_m = wid & 1;
    const int warp_n = wid >> 1;

    float d[4][4][4];
#pragma unroll
    for (int mt = 0; mt < 4; mt++)
#pragma unroll
        for (int nt = 0; nt < 4; nt++)
#pragma unroll
            for (int j = 0; j < 4; j++) d[mt][nt][j] = 0.0f;

    const int nch = K / 32;
    mm_load_chunk(smem,            0, tid, A, B, m0, n0, K);
    CP_COMMIT();
    mm_load_chunk(smem + MM_STAGE, 1, tid, A, B, m0, n0, K);
    CP_COMMIT();

    const int a_row  = warp_m * 64 + (lane & 15);
    const int a_kofs = (lane >> 4) << 4;
    const int b_row  = warp_n * 32 + ((lane >> 4) << 3) + (lane & 7);
    const int b_kofs = ((lane >> 3) & 1) << 4;

    for (int i = 0; i < nch; i++) {
        if (i + 2 < nch) {
            mm_load_chunk(smem + (uint32_t)((i + 2) % 3) * MM_STAGE, i + 2, tid,
                          A, B, m0, n0, K);
            CP_COMMIT();
            CP_WAIT2();
        } else if (i + 1 < nch) {
            CP_WAIT1();
        } else {
            CP_WAIT0();
        }
        __syncthreads();

        const uint32_t sb = smem + (uint32_t)(i % 3) * MM_STAGE;
#pragma unroll
        for (int ks = 0; ks < 2; ks++) {
            const int kb = ks * 32;
            uint32_t bq[2][4];
#pragma unroll
            for (int np = 0; np < 2; np++) {
                const uint32_t sw = sw64((uint32_t)((b_row + np * 16) * 64 + kb + b_kofs));
                LDSM4(bq[np], sb + 8192u + sw);
            }
#pragma unroll
            for (int mt = 0; mt < 4; mt++) {
                uint32_t aq[4];
                const uint32_t sw = sw64((uint32_t)((a_row + mt * 16) * 64 + kb + a_kofs));
                LDSM4(aq, sb + sw);
#pragma unroll
                for (int nt = 0; nt < 4; nt++) {
                    const int np = nt >> 1, h = (nt & 1) << 1;
                    MMA16816(d[mt][nt], aq, bq[np][h], bq[np][h + 1]);
                }
            }
        }
        __syncthreads();
    }

    // epilogue
    const int gid = lane >> 2, tig = lane & 3;
    const int mbase = m0 + warp_m * 64 + gid;
    const int nbase = nout0 + warp_n * 32 + tig * 2;
    if (mode == 0) {
#pragma unroll
        for (int mt = 0; mt < 4; mt++)
#pragma unroll
            for (int nt = 0; nt < 4; nt++) {
                const int m = mbase + mt * 16;
                const int n = nbase + nt * 8;
                *(float2*)(C + (size_t)m * ncols + n)       = make_float2(d[mt][nt][0], d[mt][nt][1]);
                *(float2*)(C + (size_t)(m + 8) * ncols + n) = make_float2(d[mt][nt][2], d[mt][nt][3]);
            }
    } else {
#pragma unroll
        for (int mt = 0; mt < 4; mt++)
#pragma unroll
            for (int nt = 0; nt < 4; nt++) {
#pragma unroll
                for (int half = 0; half < 2; half++) {
                    const int m = mbase + mt * 16 + half * 8;
                    const int n = nbase + nt * 8;
                    *(uint32_t*)(Oh + (size_t)m * ncols + n) =
                        pack2h(d[mt][nt][half * 2], d[mt][nt][half * 2 + 1]);
                }
            }
    }
}

__global__ __launch_bounds__(256, 2)
void mm_kernel(const __half* __restrict__ A,
               const __half* __restrict__ B,
               float* __restrict__ C,
               __half* __restrict__ O_a, int ncols_a,
               __half* __restrict__ O_b, int ncols_b,
               int nsplit, int K, int mode_a, int mode_b)
{
    extern __shared__ __align__(1024) char dsm[];
    const uint32_t smem = smem_to_u32(dsm);
    const int tid = threadIdx.x;
    const int m0 = blockIdx.y * 128, n0 = blockIdx.x * 128;
    const bool second = (n0 >= nsplit);

    if (!second) {
        mm_body(smem, tid, A, B, C, O_a, m0, n0, n0, ncols_a, K, mode_a);
    } else {
        mm_body(smem, tid, A, B, C, O_b, m0, n0, n0 - nsplit, ncols_b, K, mode_b);
    }
}

// ---------------- fp16 1-pass flash attention (sliding window + sink) ----------
// Q, K, V, AO: all single fp16. fp32 softmax/accum.
#define AQT 128
#define AKT 64
#define A_STAGE_OFF   32768u           // Q 32K
#define A_STAGE_BYTES 32768u           // K 16K + V 16K
#define A_SMEM_BYTES  (32768 + 2 * 32768)

__global__ __launch_bounds__(256, 1) void attn_kernel(
    const __half* __restrict__ Q_g,
    const __half* __restrict__ K_g,  const __half* __restrict__ V_g,
    __half* __restrict__ O_g)
{
    extern __shared__ __align__(1024) char dsm[];
    const uint32_t smem = smem_to_u32(dsm);
    const int tid = threadIdx.x, wid = tid >> 5, lane = tid & 31;
    const int b = blockIdx.z, h = blockIdx.y;
    const int q0 = blockIdx.x * AQT;
    const int gid = lane >> 2, tig = lane & 3;
    const int wq = wid * 16;
    const float scale = 0.08838834764831845f;

    // ---- async-load Q, panel layout lrow = (d>>6)*128 + row ----
    {
        const size_t qg = ((size_t)(b * S_LEN + q0)) * D_DIM + h * HDIM;
#pragma unroll
        for (int it = 0; it < 8; it++) {
            int ch = tid + it * 256;
            int row = ch >> 4, dblk = ch & 15;
            uint32_t lrow = (uint32_t)((dblk >> 3) * 128 + row);
            uint32_t off = lrow * 128 + (dblk & 7) * 16;
            uint32_t sw = off ^ ((off >> 3) & 0x70);
            size_t g = qg + (size_t)row * D_DIM + dblk * 8;
            CP_ASYNC16(smem + sw, (const char*)(Q_g + g));
        }
        CP_COMMIT();
    }

    const int ws = q0 - WIN + 1;
    const int tstart = (ws >= 64) ? (ws >> 6) : 1;
    const int tend = (q0 + AQT - 1) >> 6;
    const int cnt = 2 + (tend - tstart);

#define TILE_OF(j) ((j) == 0 ? 0 : (tstart + (j) - 1))
#define LOAD_KV(j) do { \
        int kb_ = TILE_OF(j) * AKT; \
        uint32_t sb_ = smem + A_STAGE_OFF + (uint32_t)((j) & 1) * A_STAGE_BYTES; \
        size_t gb_ = ((size_t)(b * S_LEN + kb_)) * D_DIM + h * HDIM; \
        _Pragma("unroll") \
        for (int it_ = 0; it_ < 4; it_++) { \
            int ch_ = tid + it_ * 256; \
            int row_ = ch_ >> 4, dblk_ = ch_ & 15; \
            uint32_t lrow_ = (uint32_t)((dblk_ >> 3) * 64 + row_); \
            uint32_t off_ = lrow_ * 128 + (dblk_ & 7) * 16; \
            uint32_t sw_ = off_ ^ ((off_ >> 3) & 0x70); \
            size_t g_ = gb_ + (size_t)row_ * D_DIM + dblk_ * 8; \
            CP_ASYNC16(sb_ + sw_,           (const char*)(K_g + g_)); \
            CP_ASYNC16(sb_ + 16384u + sw_,  (const char*)(V_g + g_)); \
        } \
        CP_COMMIT(); \
    } while (0)

    LOAD_KV(0);

    float o[16][4];
#pragma unroll
    for (int dt = 0; dt < 16; dt++)
#pragma unroll
        for (int j = 0; j < 4; j++) o[dt][j] = 0.0f;
    float m0r = -1e30f, m1r = -1e30f, l0r = 0.0f, l1r = 0.0f;

    for (int j = 0; j < cnt; j++) {
        if (j + 1 < cnt) { LOAD_KV(j + 1); CP_WAIT1(); }
        else             { CP_WAIT0(); }
        __syncthreads();

        const uint32_t sb = smem + A_STAGE_OFF + (uint32_t)(j & 1) * A_STAGE_BYTES;
        const int kb = TILE_OF(j) * AKT;

        float s[8][4];
#pragma unroll
        for (int nt = 0; nt < 8; nt++)
#pragma unroll
            for (int jj = 0; jj < 4; jj++) s[nt][jj] = 0.0f;

        // ---- S = Q K^T (1 pass) ----
#pragma unroll
        for (int ks = 0; ks < 8; ks++) {
            uint32_t aq[4];
            {
                int dd = ks * 16 + ((lane >> 4) << 3);
                int row = wq + (lane & 15);
                uint32_t lrow = (uint32_t)((dd >> 6) * 128 + row);
                uint32_t off = lrow * 128 + (dd & 63) * 2;
                uint32_t sw = off ^ ((off >> 3) & 0x70);
                LDSM4(aq, smem + sw);
            }
#pragma unroll
            for (int np = 0; np < 4; np++) {
                uint32_t bq[4];
                int key = np * 16 + ((lane >> 4) << 3) + (lane & 7);
                int dd = ks * 16 + ((lane >> 3) & 1) * 8;
                uint32_t lrow = (uint32_t)((dd >> 6) * 64 + key);
                uint32_t off = lrow * 128 + (dd & 63) * 2;
                uint32_t sw = off ^ ((off >> 3) & 0x70);
                LDSM4(bq, sb + sw);
#pragma unroll
                for (int tt = 0; tt < 2; tt++)
                    MMA16816(s[np * 2 + tt], aq, bq[2 * tt], bq[2 * tt + 1]);
            }
        }

#pragma unroll
        for (int nt = 0; nt < 8; nt++) {
            const int kc = kb + nt * 8 + tig * 2;
#pragma unroll
            for (int jj = 0; jj < 4; jj++) {
                const int q = q0 + wq + gid + ((jj >> 1) << 3);
                const int k = kc + (jj & 1);
                const bool valid = (k <= q) && ((q - k < WIN) || (k < SINK));
                s[nt][jj] = valid ? s[nt][jj] * scale : -1e30f;
            }
        }

        float tm0 = -1e30f, tm1 = -1e30f;
#pragma unroll
        for (int nt = 0; nt < 8; nt++) {
            tm0 = fmaxf(tm0, fmaxf(s[nt][0], s[nt][1]));
            tm1 = fmaxf(tm1, fmaxf(s[nt][2], s[nt][3]));
        }
        tm0 = fmaxf(tm0, __shfl_xor_sync(0xffffffffu, tm0, 1));
        tm0 = fmaxf(tm0, __shfl_xor_sync(0xffffffffu, tm0, 2));
        tm1 = fmaxf(tm1, __shfl_xor_sync(0xffffffffu, tm1, 1));
        tm1 = fmaxf(tm1, __shfl_xor_sync(0xffffffffu, tm1, 2));
        const float m0n = fmaxf(m0r, tm0), m1n = fmaxf(m1r, tm1);
        const float al0 = __expf(m0r - m0n), al1 = __expf(m1r - m1n);
        m0r = m0n; m1r = m1n;

        float rs0 = 0.0f, rs1 = 0.0f;
#pragma unroll
        for (int nt = 0; nt < 8; nt++) {
            float p0 = __expf(s[nt][0] - m0n);
            float p1 = __expf(s[nt][1] - m0n);
            float p2 = __expf(s[nt][2] - m1n);
            float p3 = __expf(s[nt][3] - m1n);
            s[nt][0] = p0; s[nt][1] = p1; s[nt][2] = p2; s[nt][3] = p3;
            rs0 += p0 + p1; rs1 += p2 + p3;
        }
        rs0 += __shfl_xor_sync(0xffffffffu, rs0, 1);
        rs0 += __shfl_xor_sync(0xffffffffu, rs0, 2);
        rs1 += __shfl_xor_sync(0xffffffffu, rs1, 1);
        rs1 += __shfl_xor_sync(0xffffffffu, rs1, 2);
        l0r = l0r * al0 + rs0;
        l1r = l1r * al1 + rs1;

#pragma unroll
        for (int dt = 0; dt < 16; dt++) {
            o[dt][0] *= al0; o[dt][1] *= al0;
            o[dt][2] *= al1; o[dt][3] *= al1;
        }

        // P -> single fp16 A-fragments (PV 1-pass)
        uint32_t ph[4][4];
#pragma unroll
        for (int ks = 0; ks < 4; ks++) {
            ph[ks][0] = pack2h(s[2 * ks][0],     s[2 * ks][1]);
            ph[ks][1] = pack2h(s[2 * ks][2],     s[2 * ks][3]);
            ph[ks][2] = pack2h(s[2 * ks + 1][0], s[2 * ks + 1][1]);
            ph[ks][3] = pack2h(s[2 * ks + 1][2], s[2 * ks + 1][3]);
        }

#pragma unroll
        for (int np = 0; np < 8; np++) {
#pragma unroll
            for (int ks = 0; ks < 4; ks++) {
                uint32_t vq[4];
                int key = ks * 16 + (lane & 7) + ((lane >> 3) & 1) * 8;
                int dd = np * 16 + ((lane >> 4) << 3);
                uint32_t lrow = (uint32_t)((dd >> 6) * 64 + key);
                uint32_t off = lrow * 128 + (dd & 63) * 2;
                uint32_t sw = off ^ ((off >> 3) & 0x70);
                LDSM4T(vq, sb + 16384u + sw);
#pragma unroll
                for (int tt = 0; tt < 2; tt++)
                    MMA16816(o[np * 2 + tt], ph[ks], vq[2 * tt], vq[2 * tt + 1]);
            }
        }
        __syncthreads();
    }

    const float inv0 = 1.0f / l0r, inv1 = 1.0f / l1r;
    const size_t ob = ((size_t)(b * S_LEN + q0 + wq)) * D_DIM + h * HDIM;
#pragma unroll
    for (int dt = 0; dt < 16; dt++) {
        const int dd = dt * 8 + tig * 2;
        *(uint32_t*)(O_g + ob + (size_t)gid * D_DIM + dd) =
            pack2h(o[dt][0] * inv0, o[dt][1] * inv0);
        *(uint32_t*)(O_g + ob + (size_t)(gid + 8) * D_DIM + dd) =
            pack2h(o[dt][2] * inv1, o[dt][3] * inv1);
    }
}

// ---------------- launch ------------------------------------------------------
extern "C" void kernel_launch(void* const* d_in, const int* in_sizes, int n_in,
                              void* d_out, int out_size)
{
    const float* x   = (const float*)d_in[0];
    const float* Wq  = (const float*)d_in[1];
    const float* Wkv = (const float*)d_in[2];
    const float* Wk  = (const float*)d_in[3];
    const float* Wv  = (const float*)d_in[4];
    const float* Wo  = (const float*)d_in[5];
    float* out = (float*)d_out;

    __half *X1, *KV1, *Q1, *K1, *V1, *AO1;
    __half *W1, *W2, *WoT;
    cudaGetSymbolAddress((void**)&X1, g_X1);
    cudaGetSymbolAddress((void**)&KV1, g_KV1);
    cudaGetSymbolAddress((void**)&Q1, g_Q1);
    cudaGetSymbolAddress((void**)&K1, g_K1);
    cudaGetSymbolAddress((void**)&V1, g_V1);
    cudaGetSymbolAddress((void**)&AO1, g_AO1);
    cudaGetSymbolAddress((void**)&W1, g_W1);
    cudaGetSymbolAddress((void**)&W2, g_W2);
    cudaGetSymbolAddress((void**)&WoT, g_WoT);

    cudaFuncSetAttribute(mm_kernel,   cudaFuncAttributeMaxDynamicSharedMemorySize, MM_SMEM_BYTES);
    cudaFuncSetAttribute(attn_kernel, cudaFuncAttributeMaxDynamicSharedMemorySize, A_SMEM_BYTES);

    const dim3 tb(32, 8);
    // --- conversions (single stream, sequential) ---
    {
        int n4 = MROWS * D_DIM / 4;
        convert_kernel<<<(n4 + 255) / 256, 256>>>((const float4*)x, (uint32_t*)X1, n4);
    }
    tsplit_kernel<<<dim3(D_DIM / 32, D_DIM / 32), tb>>>(Wq,  W1, D_DIM, D_DIM);
    tsplit_kernel<<<dim3(L_DIM / 32, D_DIM / 32), tb>>>(Wkv, W1 + (size_t)D_DIM * D_DIM, D_DIM, L_DIM);
    tsplit_kernel<<<dim3(D_DIM / 32, L_DIM / 32), tb>>>(Wk,  W2, L_DIM, D_DIM);
    tsplit_kernel<<<dim3(D_DIM / 32, L_DIM / 32), tb>>>(Wv,  W2 + (size_t)D_DIM * L_DIM, L_DIM, D_DIM);
    tsplit_kernel<<<dim3(D_DIM / 32, D_DIM / 32), tb>>>(Wo,  WoT, D_DIM, D_DIM);

    // --- [Q | KV] = X @ [Wq | Wkv]  (1-pass; single fp16 out both) ---
    mm_kernel<<<dim3((D_DIM + L_DIM) / 128, MROWS / 128), 256, MM_SMEM_BYTES>>>(
        X1, W1, nullptr,
        Q1, D_DIM, KV1, L_DIM, D_DIM, D_DIM, 2, 2);

    // --- [K | V] = KV @ [Wk | Wv]  (1-pass; single fp16 out) ---
    mm_kernel<<<dim3((2 * D_DIM) / 128, MROWS / 128), 256, MM_SMEM_BYTES>>>(
        KV1, W2, nullptr,
        K1, D_DIM, V1, D_DIM, D_DIM, L_DIM, 2, 2);

    // --- attention (all fp16, QK 1-pass, PV 1-pass) ---
    attn_kernel<<<dim3(S_LEN / AQT, NHEADS, B_SZ), 256, A_SMEM_BYTES>>>(
        Q1, K1, V1, AO1);

    // --- out = AO @ Wo (1-pass; fp32 out) ---
    mm_kernel<<<dim3(D_DIM / 128, MROWS / 128), 256, MM_SMEM_BYTES>>>(
        AO1, WoT, out,
        nullptr, D_DIM, nullptr, 0, 1 << 30, D_DIM, 0, 0);
}

// round 14
// speedup vs baseline: 1.5838x; 1.0276x over previous
#include <cuda_runtime.h>
#include <cuda_fp16.h>
#include <cstdint>

// ---------------- problem constants ----------------
#define B_SZ   2
#define S_LEN  2048
#define D_DIM  2048
#define L_DIM  512
#define NHEADS 16
#define HDIM   128
#define WIN    128
#define SINK   16
#define MROWS  (B_SZ * S_LEN)   // 4096

// ---------------- PTX helpers (base sm_103 ISA only) ----------------
__device__ __forceinline__ uint32_t smem_to_u32(const void* p) {
    uint32_t a;
    asm("{ .reg .u64 t; cvta.to.shared.u64 t, %1; cvt.u32.u64 %0, t; }" : "=r"(a) : "l"(p));
    return a;
}

#define CP_ASYNC16(saddr, gaddr) \
    asm volatile("cp.async.cg.shared.global [%0], [%1], 16;" :: "r"(saddr), "l"(gaddr) : "memory")
#define CP_COMMIT()  asm volatile("cp.async.commit_group;" ::: "memory")
#define CP_WAIT2()   asm volatile("cp.async.wait_group 2;" ::: "memory")
#define CP_WAIT1()   asm volatile("cp.async.wait_group 1;" ::: "memory")
#define CP_WAIT0()   asm volatile("cp.async.wait_group 0;" ::: "memory")

#define LDSM4(r, addr) \
    asm volatile("ldmatrix.sync.aligned.m8n8.x4.shared.b16 {%0,%1,%2,%3}, [%4];" \
        : "=r"((r)[0]), "=r"((r)[1]), "=r"((r)[2]), "=r"((r)[3]) : "r"(addr))
#define LDSM4T(r, addr) \
    asm volatile("ldmatrix.sync.aligned.m8n8.x4.trans.shared.b16 {%0,%1,%2,%3}, [%4];" \
        : "=r"((r)[0]), "=r"((r)[1]), "=r"((r)[2]), "=r"((r)[3]) : "r"(addr))

// fp16 inputs, fp32 accumulate
#define MMA16816(d, a, b0, b1) \
    asm volatile("mma.sync.aligned.m16n8k16.row.col.f32.f16.f16.f32 " \
        "{%0,%1,%2,%3},{%4,%5,%6,%7},{%8,%9},{%0,%1,%2,%3};" \
        : "+f"((d)[0]), "+f"((d)[1]), "+f"((d)[2]), "+f"((d)[3]) \
        : "r"((a)[0]), "r"((a)[1]), "r"((a)[2]), "r"((a)[3]), "r"(b0), "r"(b1))

__device__ __forceinline__ uint32_t pack2h(float x, float y) {
    __half2 h = __floats2half2_rn(x, y);
    return *(uint32_t*)&h;
}

__device__ __forceinline__ uint32_t sw64(uint32_t off) {
    return off ^ ((off >> 3) & 0x30);
}

// ---------------- scratch (device globals; all single fp16) -------------------
__device__ __align__(256) __half g_X1  [MROWS * D_DIM];
__device__ __align__(256) __half g_KV1 [MROWS * L_DIM];
__device__ __align__(256) __half g_Q1  [MROWS * D_DIM];
__device__ __align__(256) __half g_K1  [MROWS * D_DIM];
__device__ __align__(256) __half g_V1  [MROWS * D_DIM];
__device__ __align__(256) __half g_AO1 [MROWS * D_DIM];
// merged transposed weights (single fp16)
__device__ __align__(256) __half g_W1 [(D_DIM + L_DIM) * D_DIM];
__device__ __align__(256) __half g_W2 [(2 * D_DIM) * L_DIM];
__device__ __align__(256) __half g_WoT[D_DIM * D_DIM];

// ---------------- conversions ----------------
__global__ void convert_kernel(const float4* __restrict__ in,
                               uint32_t* __restrict__ out, int n4)
{
    int i = blockIdx.x * blockDim.x + threadIdx.x;
    if (i >= n4) return;
    float4 v = in[i];
    out[2 * i]     = pack2h(v.x, v.y);
    out[2 * i + 1] = pack2h(v.z, v.w);
}

// One launch converting all 5 weights: src [K,N] fp32 -> dst [N,K] fp16.
// Block ranges (32x32 tiles):
//   [0,4096)        Wq  -> W1            (K=2048, N=2048)
//   [4096,5120)     Wkv -> W1+2048*2048  (K=2048, N=512)
//   [5120,6144)     Wk  -> W2            (K=512,  N=2048)
//   [6144,7168)     Wv  -> W2+2048*512   (K=512,  N=2048)
//   [7168,11264)    Wo  -> WoT           (K=2048, N=2048)
__global__ void tsplit_all_kernel(
    const float* __restrict__ Wq, const float* __restrict__ Wkv,
    const float* __restrict__ Wk, const float* __restrict__ Wv,
    const float* __restrict__ Wo,
    __half* __restrict__ W1, __half* __restrict__ W2, __half* __restrict__ WoT)
{
    int t = blockIdx.x;
    const float* src;
    __half* dst;
    int K, N;
    if (t < 4096)      { src = Wq;  dst = W1;                               K = 2048; N = 2048; }
    else if (t < 5120) { src = Wkv; dst = W1 + (size_t)D_DIM * D_DIM;       K = 2048; N = 512;  t -= 4096; }
    else if (t < 6144) { src = Wk;  dst = W2;                               K = 512;  N = 2048; t -= 5120; }
    else if (t < 7168) { src = Wv;  dst = W2 + (size_t)D_DIM * L_DIM;       K = 512;  N = 2048; t -= 6144; }
    else               { src = Wo;  dst = WoT;                              K = 2048; N = 2048; t -= 7168; }

    const int ntx = N >> 5;
    const int nb = (t % ntx) * 32;
    const int kb = (t / ntx) * 32;

    __shared__ float tile[32][33];
    int tx = threadIdx.x, ty = threadIdx.y;
#pragma unroll
    for (int j = 0; j < 32; j += 8)
        tile[ty + j][tx] = src[(size_t)(kb + ty + j) * N + nb + tx];
    __syncthreads();
#pragma unroll
    for (int j = 0; j < 32; j += 8) {
        float v = tile[tx][ty + j];
        dst[(size_t)(nb + ty + j) * K + kb + tx] = __float2half_rn(v);
    }
}

// ---------------- fp16 1-pass HMMA GEMM (4-stage, 1 barrier/iter) -------------
// C[M,N] = A[M,K] @ B^T, B stored [N,K] single fp16. fp32 accumulate.
// 128x128 CTA tile, BK=32, 8 warps, SW64 swizzle, occ 2.
// Stage: A 8K | B 8K = 16KB; 4 stages = 64KB.
#define MM_STAGE 16384u
#define MM_SMEM_BYTES (4 * 16384)

__device__ __forceinline__ void mm_load_chunk(
    uint32_t sb, int ck, int tid,
    const __half* __restrict__ A, const __half* __restrict__ B,
    int m0, int n0, int K)
{
    const int k0 = ck * 32;
#pragma unroll
    for (int it = 0; it < 4; it++) {
        const int arr = it >> 1;                      // 0:A 1:B
        const int u   = ((it & 1) << 8) + tid;        // 0..511
        const int r   = u >> 2;                       // 0..127
        const int cb  = (u & 3) << 4;                 // byte col in 64B row
        const uint32_t sw = sw64((uint32_t)(r * 64 + cb));
        const __half* base = (arr == 0) ? A : B;
        const int row0 = (arr == 0) ? m0 : n0;
        const char* g = (const char*)(base + (size_t)(row0 + r) * K + k0) + cb;
        CP_ASYNC16(sb + (uint32_t)arr * 8192u + sw, g);
    }
}

__device__ __forceinline__ void mm_body(
    uint32_t smem, int tid,
    const __half* __restrict__ A, const __half* __restrict__ B,
    float* __restrict__ C, __half* __restrict__ Oh,
    int m0, int n0, int nout0, int ncols, int K, int mode)
    // mode: 0 = fp32 to C, 2 = single fp16 to Oh
{
    const int wid  = tid >> 5;
    const int lane = tid & 31;
    const int warp_m = wid & 1;
    const int warp_n = wid >> 1;

    float d[4][4][4];
#pragma unroll
    for (int mt = 0; mt < 4; mt++)
#pragma unroll
        for (int nt = 0; nt < 4; nt++)
#pragma unroll
            for (int j = 0; j < 4; j++) d[mt][nt][j] = 0.0f;

    const int nch = K / 32;
    mm_load_chunk(smem,                 0, tid, A, B, m0, n0, K);
    CP_COMMIT();
    mm_load_chunk(smem + MM_STAGE,      1, tid, A, B, m0, n0, K);
    CP_COMMIT();
    mm_load_chunk(smem + 2 * MM_STAGE,  2, tid, A, B, m0, n0, K);
    CP_COMMIT();

    const int a_row  = warp_m * 64 + (lane & 15);
    const int a_kofs = (lane >> 4) << 4;
    const int b_row  = warp_n * 32 + ((lane >> 4) << 3) + (lane & 7);
    const int b_kofs = ((lane >> 3) & 1) << 4;

    for (int i = 0; i < nch; i++) {
        // chunk i ready after allowing remaining outstanding groups
        if (i + 2 < nch)      CP_WAIT2();
        else if (i + 1 < nch) CP_WAIT1();
        else                  CP_WAIT0();
        __syncthreads();      // all warps past compute(i-1); smem of chunk i visible

        // issue next load AFTER barrier: targets stage (i+3)%4 == (i-1)%4, now free
        if (i + 3 < nch) {
            mm_load_chunk(smem + (uint32_t)((i + 3) & 3) * MM_STAGE, i + 3, tid,
                          A, B, m0, n0, K);
            CP_COMMIT();
        }

        const uint32_t sb = smem + (uint32_t)(i & 3) * MM_STAGE;
#pragma unroll
        for (int ks = 0; ks < 2; ks++) {
            const int kb = ks * 32;
            uint32_t bq[2][4];
#pragma unroll
            for (int np = 0; np < 2; np++) {
                const uint32_t sw = sw64((uint32_t)((b_row + np * 16) * 64 + kb + b_kofs));
                LDSM4(bq[np], sb + 8192u + sw);
            }
#pragma unroll
            for (int mt = 0; mt < 4; mt++) {
                uint32_t aq[4];
                const uint32_t sw = sw64((uint32_t)((a_row + mt * 16) * 64 + kb + a_kofs));
                LDSM4(aq, sb + sw);
#pragma unroll
                for (int nt = 0; nt < 4; nt++) {
                    const int np = nt >> 1, h = (nt & 1) << 1;
                    MMA16816(d[mt][nt], aq, bq[np][h], bq[np][h + 1]);
                }
            }
        }
        // no trailing barrier: next overwrite of stage (i)%4 happens in iter i+1's
        // load of chunk i+4 — but that is stage (i+4)%4 == i%4 only after iter i+1's
        // barrier, which all warps reach only after finishing this compute.
    }

    // epilogue
    const int gid = lane >> 2, tig = lane & 3;
    const int mbase = m0 + warp_m * 64 + gid;
    const int nbase = nout0 + warp_n * 32 + tig * 2;
    if (mode == 0) {
#pragma unroll
        for (int mt = 0; mt < 4; mt++)
#pragma unroll
            for (int nt = 0; nt < 4; nt++) {
                const int m = mbase + mt * 16;
                const int n = nbase + nt * 8;
                *(float2*)(C + (size_t)m * ncols + n)       = make_float2(d[mt][nt][0], d[mt][nt][1]);
                *(float2*)(C + (size_t)(m + 8) * ncols + n) = make_float2(d[mt][nt][2], d[mt][nt][3]);
            }
    } else {
#pragma unroll
        for (int mt = 0; mt < 4; mt++)
#pragma unroll
            for (int nt = 0; nt < 4; nt++) {
#pragma unroll
                for (int half = 0; half < 2; half++) {
                    const int m = mbase + mt * 16 + half * 8;
                    const int n = nbase + nt * 8;
                    *(uint32_t*)(Oh + (size_t)m * ncols + n) =
                        pack2h(d[mt][nt][half * 2], d[mt][nt][half * 2 + 1]);
                }
            }
    }
}

__global__ __launch_bounds__(256, 2)
void mm_kernel(const __half* __restrict__ A,
               const __half* __restrict__ B,
               float* __restrict__ C,
               __half* __restrict__ O_a, int ncols_a,
               __half* __restrict__ O_b, int ncols_b,
               int nsplit, int K, int mode_a, int mode_b)
{
    extern __shared__ __align__(1024) char dsm[];
    const uint32_t smem = smem_to_u32(dsm);
    const int tid = threadIdx.x;
    const int m0 = blockIdx.y * 128, n0 = blockIdx.x * 128;
    const bool second = (n0 >= nsplit);

    if (!second) {
        mm_body(smem, tid, A, B, C, O_a, m0, n0, n0, ncols_a, K, mode_a);
    } else {
        mm_body(smem, tid, A, B, C, O_b, m0, n0, n0 - nsplit, ncols_b, K, mode_b);
    }
}

// ---------------- fp16 1-pass flash attention (sliding window + sink) ----------
#define AQT 128
#define AKT 64
#define A_STAGE_OFF   32768u           // Q 32K
#define A_STAGE_BYTES 32768u           // K 16K + V 16K
#define A_SMEM_BYTES  (32768 + 2 * 32768)

__global__ __launch_bounds__(256, 1) void attn_kernel(
    const __half* __restrict__ Q_g,
    const __half* __restrict__ K_g,  const __half* __restrict__ V_g,
    __half* __restrict__ O_g)
{
    extern __shared__ __align__(1024) char dsm[];
    const uint32_t smem = smem_to_u32(dsm);
    const int tid = threadIdx.x, wid = tid >> 5, lane = tid & 31;
    const int b = blockIdx.z, h = blockIdx.y;
    const int q0 = blockIdx.x * AQT;
    const int gid = lane >> 2, tig = lane & 3;
    const int wq = wid * 16;
    const float scale = 0.08838834764831845f;

    {
        const size_t qg = ((size_t)(b * S_LEN + q0)) * D_DIM + h * HDIM;
#pragma unroll
        for (int it = 0; it < 8; it++) {
            int ch = tid + it * 256;
            int row = ch >> 4, dblk = ch & 15;
            uint32_t lrow = (uint32_t)((dblk >> 3) * 128 + row);
            uint32_t off = lrow * 128 + (dblk & 7) * 16;
            uint32_t sw = off ^ ((off >> 3) & 0x70);
            size_t g = qg + (size_t)row * D_DIM + dblk * 8;
            CP_ASYNC16(smem + sw, (const char*)(Q_g + g));
        }
        CP_COMMIT();
    }

    const int ws = q0 - WIN + 1;
    const int tstart = (ws >= 64) ? (ws >> 6) : 1;
    const int tend = (q0 + AQT - 1) >> 6;
    const int cnt = 2 + (tend - tstart);

#define TILE_OF(j) ((j) == 0 ? 0 : (tstart + (j) - 1))
#define LOAD_KV(j) do { \
        int kb_ = TILE_OF(j) * AKT; \
        uint32_t sb_ = smem + A_STAGE_OFF + (uint32_t)((j) & 1) * A_STAGE_BYTES; \
        size_t gb_ = ((size_t)(b * S_LEN + kb_)) * D_DIM + h * HDIM; \
        _Pragma("unroll") \
        for (int it_ = 0; it_ < 4; it_++) { \
            int ch_ = tid + it_ * 256; \
            int row_ = ch_ >> 4, dblk_ = ch_ & 15; \
            uint32_t lrow_ = (uint32_t)((dblk_ >> 3) * 64 + row_); \
            uint32_t off_ = lrow_ * 128 + (dblk_ & 7) * 16; \
            uint32_t sw_ = off_ ^ ((off_ >> 3) & 0x70); \
            size_t g_ = gb_ + (size_t)row_ * D_DIM + dblk_ * 8; \
            CP_ASYNC16(sb_ + sw_,           (const char*)(K_g + g_)); \
            CP_ASYNC16(sb_ + 16384u + sw_,  (const char*)(V_g + g_)); \
        } \
        CP_COMMIT(); \
    } while (0)

    LOAD_KV(0);

    float o[16][4];
#pragma unroll
    for (int dt = 0; dt < 16; dt++)
#pragma unroll
        for (int j = 0; j < 4; j++) o[dt][j] = 0.0f;
    float m0r = -1e30f, m1r = -1e30f, l0r = 0.0f, l1r = 0.0f;

    for (int j = 0; j < cnt; j++) {
        if (j + 1 < cnt) { LOAD_KV(j + 1); CP_WAIT1(); }
        else             { CP_WAIT0(); }
        __syncthreads();

        const uint32_t sb = smem + A_STAGE_OFF + (uint32_t)(j & 1) * A_STAGE_BYTES;
        const int kb = TILE_OF(j) * AKT;

        float s[8][4];
#pragma unroll
        for (int nt = 0; nt < 8; nt++)
#pragma unroll
            for (int jj = 0; jj < 4; jj++) s[nt][jj] = 0.0f;

#pragma unroll
        for (int ks = 0; ks < 8; ks++) {
            uint32_t aq[4];
            {
                int dd = ks * 16 + ((lane >> 4) << 3);
                int row = wq + (lane & 15);
                uint32_t lrow = (uint32_t)((dd >> 6) * 128 + row);
                uint32_t off = lrow * 128 + (dd & 63) * 2;
                uint32_t sw = off ^ ((off >> 3) & 0x70);
                LDSM4(aq, smem + sw);
            }
#pragma unroll
            for (int np = 0; np < 4; np++) {
                uint32_t bq[4];
                int key = np * 16 + ((lane >> 4) << 3) + (lane & 7);
                int dd = ks * 16 + ((lane >> 3) & 1) * 8;
                uint32_t lrow = (uint32_t)((dd >> 6) * 64 + key);
                uint32_t off = lrow * 128 + (dd & 63) * 2;
                uint32_t sw = off ^ ((off >> 3) & 0x70);
                LDSM4(bq, sb + sw);
#pragma unroll
                for (int tt = 0; tt < 2; tt++)
                    MMA16816(s[np * 2 + tt], aq, bq[2 * tt], bq[2 * tt + 1]);
            }
        }

#pragma unroll
        for (int nt = 0; nt < 8; nt++) {
            const int kc = kb + nt * 8 + tig * 2;
#pragma unroll
            for (int jj = 0; jj < 4; jj++) {
                const int q = q0 + wq + gid + ((jj >> 1) << 3);
                const int k = kc + (jj & 1);
                const bool valid = (k <= q) && ((q - k < WIN) || (k < SINK));
                s[nt][jj] = valid ? s[nt][jj] * scale : -1e30f;
            }
        }

        float tm0 = -1e30f, tm1 = -1e30f;
#pragma unroll
        for (int nt = 0; nt < 8; nt++) {
            tm0 = fmaxf(tm0, fmaxf(s[nt][0], s[nt][1]));
            tm1 = fmaxf(tm1, fmaxf(s[nt][2], s[nt][3]));
        }
        tm0 = fmaxf(tm0, __shfl_xor_sync(0xffffffffu, tm0, 1));
        tm0 = fmaxf(tm0, __shfl_xor_sync(0xffffffffu, tm0, 2));
        tm1 = fmaxf(tm1, __shfl_xor_sync(0xffffffffu, tm1, 1));
        tm1 = fmaxf(tm1, __shfl_xor_sync(0xffffffffu, tm1, 2));
        const float m0n = fmaxf(m0r, tm0), m1n = fmaxf(m1r, tm1);
        const float al0 = __expf(m0r - m0n), al1 = __expf(m1r - m1n);
        m0r = m0n; m1r = m1n;

        float rs0 = 0.0f, rs1 = 0.0f;
#pragma unroll
        for (int nt = 0; nt < 8; nt++) {
            float p0 = __expf(s[nt][0] - m0n);
            float p1 = __expf(s[nt][1] - m0n);
            float p2 = __expf(s[nt][2] - m1n);
            float p3 = __expf(s[nt][3] - m1n);
            s[nt][0] = p0; s[nt][1] = p1; s[nt][2] = p2; s[nt][3] = p3;
            rs0 += p0 + p1; rs1 += p2 + p3;
        }
        rs0 += __shfl_xor_sync(0xffffffffu, rs0, 1);
        rs0 += __shfl_xor_sync(0xffffffffu, rs0, 2);
        rs1 += __shfl_xor_sync(0xffffffffu, rs1, 1);
        rs1 += __shfl_xor_sync(0xffffffffu, rs1, 2);
        l0r = l0r * al0 + rs0;
        l1r = l1r * al1 + rs1;

#pragma unroll
        for (int dt = 0; dt < 16; dt++) {
            o[dt][0] *= al0; o[dt][1] *= al0;
            o[dt][2] *= al1; o[dt][3] *= al1;
        }

        uint32_t ph[4][4];
#pragma unroll
        for (int ks = 0; ks < 4; ks++) {
            ph[ks][0] = pack2h(s[2 * ks][0],     s[2 * ks][1]);
            ph[ks][1] = pack2h(s[2 * ks][2],     s[2 * ks][3]);
            ph[ks][2] = pack2h(s[2 * ks + 1][0], s[2 * ks + 1][1]);
            ph[ks][3] = pack2h(s[2 * ks + 1][2], s[2 * ks + 1][3]);
        }

#pragma unroll
        for (int np = 0; np < 8; np++) {
#pragma unroll
            for (int ks = 0; ks < 4; ks++) {
                uint32_t vq[4];
                int key = ks * 16 + (lane & 7) + ((lane >> 3) & 1) * 8;
                int dd = np * 16 + ((lane >> 4) << 3);
                uint32_t lrow = (uint32_t)((dd >> 6) * 64 + key);
                uint32_t off = lrow * 128 + (dd & 63) * 2;
                uint32_t sw = off ^ ((off >> 3) & 0x70);
                LDSM4T(vq, sb + 16384u + sw);
#pragma unroll
                for (int tt = 0; tt < 2; tt++)
                    MMA16816(o[np * 2 + tt], ph[ks], vq[2 * tt], vq[2 * tt + 1]);
            }
        }
        __syncthreads();
    }

    const float inv0 = 1.0f / l0r, inv1 = 1.0f / l1r;
    const size_t ob = ((size_t)(b * S_LEN + q0 + wq)) * D_DIM + h * HDIM;
#pragma unroll
    for (int dt = 0; dt < 16; dt++) {
        const int dd = dt * 8 + tig * 2;
        *(uint32_t*)(O_g + ob + (size_t)gid * D_DIM + dd) =
            pack2h(o[dt][0] * inv0, o[dt][1] * inv0);
        *(uint32_t*)(O_g + ob + (size_t)(gid + 8) * D_DIM + dd) =
            pack2h(o[dt][2] * inv1, o[dt][3] * inv1);
    }
}

// ---------------- launch ------------------------------------------------------
extern "C" void kernel_launch(void* const* d_in, const int* in_sizes, int n_in,
                              void* d_out, int out_size)
{
    const float* x   = (const float*)d_in[0];
    const float* Wq  = (const float*)d_in[1];
    const float* Wkv = (const float*)d_in[2];
    const float* Wk  = (const float*)d_in[3];
    const float* Wv  = (const float*)d_in[4];
    const float* Wo  = (const float*)d_in[5];
    float* out = (float*)d_out;

    __half *X1, *KV1, *Q1, *K1, *V1, *AO1;
    __half *W1, *W2, *WoT;
    cudaGetSymbolAddress((void**)&X1, g_X1);
    cudaGetSymbolAddress((void**)&KV1, g_KV1);
    cudaGetSymbolAddress((void**)&Q1, g_Q1);
    cudaGetSymbolAddress((void**)&K1, g_K1);
    cudaGetSymbolAddress((void**)&V1, g_V1);
    cudaGetSymbolAddress((void**)&AO1, g_AO1);
    cudaGetSymbolAddress((void**)&W1, g_W1);
    cudaGetSymbolAddress((void**)&W2, g_W2);
    cudaGetSymbolAddress((void**)&WoT, g_WoT);

    cudaFuncSetAttribute(mm_kernel,   cudaFuncAttributeMaxDynamicSharedMemorySize, MM_SMEM_BYTES);
    cudaFuncSetAttribute(attn_kernel, cudaFuncAttributeMaxDynamicSharedMemorySize, A_SMEM_BYTES);

    // --- conversions ---
    {
        int n4 = MROWS * D_DIM / 4;
        convert_kernel<<<(n4 + 255) / 256, 256>>>((const float4*)x, (uint32_t*)X1, n4);
    }
    tsplit_all_kernel<<<11264, dim3(32, 8)>>>(Wq, Wkv, Wk, Wv, Wo, W1, W2, WoT);

    // --- [Q | KV] = X @ [Wq | Wkv]  (1-pass; single fp16 out both) ---
    mm_kernel<<<dim3((D_DIM + L_DIM) / 128, MROWS / 128), 256, MM_SMEM_BYTES>>>(
        X1, W1, nullptr,
        Q1, D_DIM, KV1, L_DIM, D_DIM, D_DIM, 2, 2);

    // --- [K | V] = KV @ [Wk | Wv]  (1-pass; single fp16 out) ---
    mm_kernel<<<dim3((2 * D_DIM) / 128, MROWS / 128), 256, MM_SMEM_BYTES>>>(
        KV1, W2, nullptr,
        K1, D_DIM, V1, D_DIM, D_DIM, L_DIM, 2, 2);

    // --- attention (all fp16, 1-pass QK and PV) ---
    attn_kernel<<<dim3(S_LEN / AQT, NHEADS, B_SZ), 256, A_SMEM_BYTES>>>(
        Q1, K1, V1, AO1);

    // --- out = AO @ Wo (1-pass; fp32 out) ---
    mm_kernel<<<dim3(D_DIM / 128, MROWS / 128), 256, MM_SMEM_BYTES>>>(
        AO1, WoT, out,
        nullptr, D_DIM, nullptr, 0, 1 << 30, D_DIM, 0, 0);
}

// round 15
// speedup vs baseline: 1.6635x; 1.0503x over previous
#include <cuda_runtime.h>
#include <cuda_fp16.h>
#include <cstdint>

// ---------------- problem constants ----------------
#define B_SZ   2
#define S_LEN  2048
#define D_DIM  2048
#define L_DIM  512
#define NHEADS 16
#define HDIM   128
#define WIN    128
#define SINK   16
#define MROWS  (B_SZ * S_LEN)   // 4096

// ---------------- PTX helpers (base sm_103 ISA only) ----------------
__device__ __forceinline__ uint32_t smem_to_u32(const void* p) {
    uint32_t a;
    asm("{ .reg .u64 t; cvta.to.shared.u64 t, %1; cvt.u32.u64 %0, t; }" : "=r"(a) : "l"(p));
    return a;
}

#define CP_ASYNC16(saddr, gaddr) \
    asm volatile("cp.async.cg.shared.global [%0], [%1], 16;" :: "r"(saddr), "l"(gaddr) : "memory")
#define CP_COMMIT()  asm volatile("cp.async.commit_group;" ::: "memory")
#define CP_WAIT1()   asm volatile("cp.async.wait_group 1;" ::: "memory")
#define CP_WAIT0()   asm volatile("cp.async.wait_group 0;" ::: "memory")

#define LDSM4(r, addr) \
    asm volatile("ldmatrix.sync.aligned.m8n8.x4.shared.b16 {%0,%1,%2,%3}, [%4];" \
        : "=r"((r)[0]), "=r"((r)[1]), "=r"((r)[2]), "=r"((r)[3]) : "r"(addr))
#define LDSM4T(r, addr) \
    asm volatile("ldmatrix.sync.aligned.m8n8.x4.trans.shared.b16 {%0,%1,%2,%3}, [%4];" \
        : "=r"((r)[0]), "=r"((r)[1]), "=r"((r)[2]), "=r"((r)[3]) : "r"(addr))

// fp16 inputs, fp32 accumulate
#define MMA16816(d, a, b0, b1) \
    asm volatile("mma.sync.aligned.m16n8k16.row.col.f32.f16.f16.f32 " \
        "{%0,%1,%2,%3},{%4,%5,%6,%7},{%8,%9},{%0,%1,%2,%3};" \
        : "+f"((d)[0]), "+f"((d)[1]), "+f"((d)[2]), "+f"((d)[3]) \
        : "r"((a)[0]), "r"((a)[1]), "r"((a)[2]), "r"((a)[3]), "r"(b0), "r"(b1))

__device__ __forceinline__ uint32_t pack2h(float x, float y) {
    __half2 h = __floats2half2_rn(x, y);
    return *(uint32_t*)&h;
}

#define SW128(off) ((off) ^ (((off) >> 3) & 0x70))

// ---------------- scratch (device globals; all single fp16) -------------------
__device__ __align__(256) __half g_X1  [MROWS * D_DIM];
__device__ __align__(256) __half g_KV1 [MROWS * L_DIM];
__device__ __align__(256) __half g_Q1  [MROWS * D_DIM];
__device__ __align__(256) __half g_K1  [MROWS * D_DIM];
__device__ __align__(256) __half g_V1  [MROWS * D_DIM];
__device__ __align__(256) __half g_AO1 [MROWS * D_DIM];
// merged transposed weights (single fp16)
__device__ __align__(256) __half g_W1 [(D_DIM + L_DIM) * D_DIM];
__device__ __align__(256) __half g_W2 [(2 * D_DIM) * L_DIM];
__device__ __align__(256) __half g_WoT[D_DIM * D_DIM];

// ---------------- conversions ----------------
__global__ void convert_kernel(const float4* __restrict__ in,
                               uint32_t* __restrict__ out, int n4)
{
    int i = blockIdx.x * blockDim.x + threadIdx.x;
    if (i >= n4) return;
    float4 v = in[i];
    out[2 * i]     = pack2h(v.x, v.y);
    out[2 * i + 1] = pack2h(v.z, v.w);
}

// One launch converting all 5 weights: src [K,N] fp32 -> dst [N,K] fp16.
__global__ void tsplit_all_kernel(
    const float* __restrict__ Wq, const float* __restrict__ Wkv,
    const float* __restrict__ Wk, const float* __restrict__ Wv,
    const float* __restrict__ Wo,
    __half* __restrict__ W1, __half* __restrict__ W2, __half* __restrict__ WoT)
{
    int t = blockIdx.x;
    const float* src;
    __half* dst;
    int K, N;
    if (t < 4096)      { src = Wq;  dst = W1;                          K = 2048; N = 2048; }
    else if (t < 5120) { src = Wkv; dst = W1 + (size_t)D_DIM * D_DIM;  K = 2048; N = 512;  t -= 4096; }
    else if (t < 6144) { src = Wk;  dst = W2;                          K = 512;  N = 2048; t -= 5120; }
    else if (t < 7168) { src = Wv;  dst = W2 + (size_t)D_DIM * L_DIM;  K = 512;  N = 2048; t -= 6144; }
    else               { src = Wo;  dst = WoT;                         K = 2048; N = 2048; t -= 7168; }

    const int ntx = N >> 5;
    const int nb = (t % ntx) * 32;
    const int kb = (t / ntx) * 32;

    __shared__ float tile[32][33];
    int tx = threadIdx.x, ty = threadIdx.y;
#pragma unroll
    for (int j = 0; j < 32; j += 8)
        tile[ty + j][tx] = src[(size_t)(kb + ty + j) * N + nb + tx];
    __syncthreads();
#pragma unroll
    for (int j = 0; j < 32; j += 8) {
        float v = tile[tx][ty + j];
        dst[(size_t)(nb + ty + j) * K + kb + tx] = __float2half_rn(v);
    }
}

// ---------------- fp16 1-pass HMMA GEMM (BK=64, 3-stage, 1 barrier/iter) ------
// C[M,N] = A[M,K] @ B^T, B stored [N,K] single fp16. fp32 accumulate.
// 128x128 CTA tile, BK=64, 8 warps, SW128 swizzle (128B rows), occ 2.
// Stage: A 16K | B 16K = 32KB; 3 stages = 96KB.
#define MM_STAGE 32768u
#define MM_SMEM_BYTES (3 * 32768)

__device__ __forceinline__ void mm_load_chunk(
    uint32_t sb, int ck, int tid,
    const __half* __restrict__ A, const __half* __restrict__ B,
    int m0, int n0, int K)
{
    const int k0 = ck * 64;
#pragma unroll
    for (int it = 0; it < 8; it++) {
        const int arr = it >> 2;                      // 0:A 1:B
        const int u   = ((it & 3) << 8) + tid;        // 0..1023
        const int r   = u >> 3;                       // 0..127
        const int cb  = (u & 7) << 4;                 // byte col in 128B row
        const uint32_t sw = SW128((uint32_t)(r * 128 + cb));
        const __half* base = (arr == 0) ? A : B;
        const int row0 = (arr == 0) ? m0 : n0;
        const char* g = (const char*)(base + (size_t)(row0 + r) * K + k0) + cb;
        CP_ASYNC16(sb + (uint32_t)arr * 16384u + sw, g);
    }
}

__device__ __forceinline__ void mm_body(
    uint32_t smem, int tid,
    const __half* __restrict__ A, const __half* __restrict__ B,
    float* __restrict__ C, __half* __restrict__ Oh,
    int m0, int n0, int nout0, int ncols, int K, int mode)
    // mode: 0 = fp32 to C, 2 = single fp16 to Oh
{
    const int wid  = tid >> 5;
    const int lane = tid & 31;
    const int warp_m = wid & 1;
    const int warp_n = wid >> 1;

    float d[4][4][4];
#pragma unroll
    for (int mt = 0; mt < 4; mt++)
#pragma unroll
        for (int nt = 0; nt < 4; nt++)
#pragma unroll
            for (int j = 0; j < 4; j++) d[mt][nt][j] = 0.0f;

    const int nch = K / 64;
    mm_load_chunk(smem,            0, tid, A, B, m0, n0, K);
    CP_COMMIT();
    mm_load_chunk(smem + MM_STAGE, 1, tid, A, B, m0, n0, K);
    CP_COMMIT();

    const int a_row  = warp_m * 64 + (lane & 15);
    const int a_kofs = (lane >> 4) << 4;
    const int b_row  = warp_n * 32 + ((lane >> 4) << 3) + (lane & 7);
    const int b_kofs = ((lane >> 3) & 1) << 4;

    for (int i = 0; i < nch; i++) {
        if (i + 1 < nch) CP_WAIT1();
        else             CP_WAIT0();
        __syncthreads();      // all warps past compute(i-1); chunk i visible

        // issue next load AFTER barrier: targets stage (i+2)%3 == (i-1)%3, now free
        if (i + 2 < nch) {
            mm_load_chunk(smem + (uint32_t)((i + 2) % 3) * MM_STAGE, i + 2, tid,
                          A, B, m0, n0, K);
            CP_COMMIT();
        }

        const uint32_t sb = smem + (uint32_t)(i % 3) * MM_STAGE;
#pragma unroll
        for (int ks = 0; ks < 4; ks++) {
            const int kb = ks * 32;
            uint32_t bq[2][4];
#pragma unroll
            for (int np = 0; np < 2; np++) {
                const uint32_t sw = SW128((uint32_t)((b_row + np * 16) * 128 + kb + b_kofs));
                LDSM4(bq[np], sb + 16384u + sw);
            }
#pragma unroll
            for (int mt = 0; mt < 4; mt++) {
                uint32_t aq[4];
                const uint32_t sw = SW128((uint32_t)((a_row + mt * 16) * 128 + kb + a_kofs));
                LDSM4(aq, sb + sw);
#pragma unroll
                for (int nt = 0; nt < 4; nt++) {
                    const int np = nt >> 1, h = (nt & 1) << 1;
                    MMA16816(d[mt][nt], aq, bq[np][h], bq[np][h + 1]);
                }
            }
        }
    }

    // epilogue
    const int gid = lane >> 2, tig = lane & 3;
    const int mbase = m0 + warp_m * 64 + gid;
    const int nbase = nout0 + warp_n * 32 + tig * 2;
    if (mode == 0) {
#pragma unroll
        for (int mt = 0; mt < 4; mt++)
#pragma unroll
            for (int nt = 0; nt < 4; nt++) {
                const int m = mbase + mt * 16;
                const int n = nbase + nt * 8;
                *(float2*)(C + (size_t)m * ncols + n)       = make_float2(d[mt][nt][0], d[mt][nt][1]);
                *(float2*)(C + (size_t)(m + 8) * ncols + n) = make_float2(d[mt][nt][2], d[mt][nt][3]);
            }
    } else {
#pragma unroll
        for (int mt = 0; mt < 4; mt++)
#pragma unroll
            for (int nt = 0; nt < 4; nt++) {
#pragma unroll
                for (int half = 0; half < 2; half++) {
                    const int m = mbase + mt * 16 + half * 8;
                    const int n = nbase + nt * 8;
                    *(uint32_t*)(Oh + (size_t)m * ncols + n) =
                        pack2h(d[mt][nt][half * 2], d[mt][nt][half * 2 + 1]);
                }
            }
    }
}

__global__ __launch_bounds__(256, 2)
void mm_kernel(const __half* __restrict__ A,
               const __half* __restrict__ B,
               float* __restrict__ C,
               __half* __restrict__ O_a, int ncols_a,
               __half* __restrict__ O_b, int ncols_b,
               int nsplit, int K, int mode_a, int mode_b)
{
    extern __shared__ __align__(1024) char dsm[];
    const uint32_t smem = smem_to_u32(dsm);
    const int tid = threadIdx.x;
    const int m0 = blockIdx.y * 128, n0 = blockIdx.x * 128;
    const bool second = (n0 >= nsplit);

    if (!second) {
        mm_body(smem, tid, A, B, C, O_a, m0, n0, n0, ncols_a, K, mode_a);
    } else {
        mm_body(smem, tid, A, B, C, O_b, m0, n0, n0 - nsplit, ncols_b, K, mode_b);
    }
}

// ---------------- fp16 1-pass flash attention (sliding window + sink) ----------
#define AQT 128
#define AKT 64
#define A_STAGE_OFF   32768u           // Q 32K
#define A_STAGE_BYTES 32768u           // K 16K + V 16K
#define A_SMEM_BYTES  (32768 + 2 * 32768)

__global__ __launch_bounds__(256, 1) void attn_kernel(
    const __half* __restrict__ Q_g,
    const __half* __restrict__ K_g,  const __half* __restrict__ V_g,
    __half* __restrict__ O_g)
{
    extern __shared__ __align__(1024) char dsm[];
    const uint32_t smem = smem_to_u32(dsm);
    const int tid = threadIdx.x, wid = tid >> 5, lane = tid & 31;
    const int b = blockIdx.z, h = blockIdx.y;
    const int q0 = blockIdx.x * AQT;
    const int gid = lane >> 2, tig = lane & 3;
    const int wq = wid * 16;
    const float scale = 0.08838834764831845f;

    {
        const size_t qg = ((size_t)(b * S_LEN + q0)) * D_DIM + h * HDIM;
#pragma unroll
        for (int it = 0; it < 8; it++) {
            int ch = tid + it * 256;
            int row = ch >> 4, dblk = ch & 15;
            uint32_t lrow = (uint32_t)((dblk >> 3) * 128 + row);
            uint32_t off = lrow * 128 + (dblk & 7) * 16;
            uint32_t sw = SW128(off);
            size_t g = qg + (size_t)row * D_DIM + dblk * 8;
            CP_ASYNC16(smem + sw, (const char*)(Q_g + g));
        }
        CP_COMMIT();
    }

    const int ws = q0 - WIN + 1;
    const int tstart = (ws >= 64) ? (ws >> 6) : 1;
    const int tend = (q0 + AQT - 1) >> 6;
    const int cnt = 2 + (tend - tstart);

#define TILE_OF(j) ((j) == 0 ? 0 : (tstart + (j) - 1))
#define LOAD_KV(j) do { \
        int kb_ = TILE_OF(j) * AKT; \
        uint32_t sb_ = smem + A_STAGE_OFF + (uint32_t)((j) & 1) * A_STAGE_BYTES; \
        size_t gb_ = ((size_t)(b * S_LEN + kb_)) * D_DIM + h * HDIM; \
        _Pragma("unroll") \
        for (int it_ = 0; it_ < 4; it_++) { \
            int ch_ = tid + it_ * 256; \
            int row_ = ch_ >> 4, dblk_ = ch_ & 15; \
            uint32_t lrow_ = (uint32_t)((dblk_ >> 3) * 64 + row_); \
            uint32_t off_ = lrow_ * 128 + (dblk_ & 7) * 16; \
            uint32_t sw_ = SW128(off_); \
            size_t g_ = gb_ + (size_t)row_ * D_DIM + dblk_ * 8; \
            CP_ASYNC16(sb_ + sw_,           (const char*)(K_g + g_)); \
            CP_ASYNC16(sb_ + 16384u + sw_,  (const char*)(V_g + g_)); \
        } \
        CP_COMMIT(); \
    } while (0)

    LOAD_KV(0);

    float o[16][4];
#pragma unroll
    for (int dt = 0; dt < 16; dt++)
#pragma unroll
        for (int j = 0; j < 4; j++) o[dt][j] = 0.0f;
    float m0r = -1e30f, m1r = -1e30f, l0r = 0.0f, l1r = 0.0f;

    for (int j = 0; j < cnt; j++) {
        if (j + 1 < cnt) { LOAD_KV(j + 1); CP_WAIT1(); }
        else             { CP_WAIT0(); }
        __syncthreads();

        const uint32_t sb = smem + A_STAGE_OFF + (uint32_t)(j & 1) * A_STAGE_BYTES;
        const int kb = TILE_OF(j) * AKT;

        float s[8][4];
#pragma unroll
        for (int nt = 0; nt < 8; nt++)
#pragma unroll
            for (int jj = 0; jj < 4; jj++) s[nt][jj] = 0.0f;

#pragma unroll
        for (int ks = 0; ks < 8; ks++) {
            uint32_t aq[4];
            {
                int dd = ks * 16 + ((lane >> 4) << 3);
                int row = wq + (lane & 15);
                uint32_t lrow = (uint32_t)((dd >> 6) * 128 + row);
                uint32_t off = lrow * 128 + (dd & 63) * 2;
                uint32_t sw = SW128(off);
                LDSM4(aq, smem + sw);
            }
#pragma unroll
            for (int np = 0; np < 4; np++) {
                uint32_t bq[4];
                int key = np * 16 + ((lane >> 4) << 3) + (lane & 7);
                int dd = ks * 16 + ((lane >> 3) & 1) * 8;
                uint32_t lrow = (uint32_t)((dd >> 6) * 64 + key);
                uint32_t off = lrow * 128 + (dd & 63) * 2;
                uint32_t sw = SW128(off);
                LDSM4(bq, sb + sw);
#pragma unroll
                for (int tt = 0; tt < 2; tt++)
                    MMA16816(s[np * 2 + tt], aq, bq[2 * tt], bq[2 * tt + 1]);
            }
        }

#pragma unroll
        for (int nt = 0; nt < 8; nt++) {
            const int kc = kb + nt * 8 + tig * 2;
#pragma unroll
            for (int jj = 0; jj < 4; jj++) {
                const int q = q0 + wq + gid + ((jj >> 1) << 3);
                const int k = kc + (jj & 1);
                const bool valid = (k <= q) && ((q - k < WIN) || (k < SINK));
                s[nt][jj] = valid ? s[nt][jj] * scale : -1e30f;
            }
        }

        float tm0 = -1e30f, tm1 = -1e30f;
#pragma unroll
        for (int nt = 0; nt < 8; nt++) {
            tm0 = fmaxf(tm0, fmaxf(s[nt][0], s[nt][1]));
            tm1 = fmaxf(tm1, fmaxf(s[nt][2], s[nt][3]));
        }
        tm0 = fmaxf(tm0, __shfl_xor_sync(0xffffffffu, tm0, 1));
        tm0 = fmaxf(tm0, __shfl_xor_sync(0xffffffffu, tm0, 2));
        tm1 = fmaxf(tm1, __shfl_xor_sync(0xffffffffu, tm1, 1));
        tm1 = fmaxf(tm1, __shfl_xor_sync(0xffffffffu, tm1, 2));
        const float m0n = fmaxf(m0r, tm0), m1n = fmaxf(m1r, tm1);
        const float al0 = __expf(m0r - m0n), al1 = __expf(m1r - m1n);
        m0r = m0n; m1r = m1n;

        float rs0 = 0.0f, rs1 = 0.0f;
#pragma unroll
        for (int nt = 0; nt < 8; nt++) {
            float p0 = __expf(s[nt][0] - m0n);
            float p1 = __expf(s[nt][1] - m0n);
            float p2 = __expf(s[nt][2] - m1n);
            float p3 = __expf(s[nt][3] - m1n);
            s[nt][0] = p0; s[nt][1] = p1; s[nt][2] = p2; s[nt][3] = p3;
            rs0 += p0 + p1; rs1 += p2 + p3;
        }
        rs0 += __shfl_xor_sync(0xffffffffu, rs0, 1);
        rs0 += __shfl_xor_sync(0xffffffffu, rs0, 2);
        rs1 += __shfl_xor_sync(0xffffffffu, rs1, 1);
        rs1 += __shfl_xor_sync(0xffffffffu, rs1, 2);
        l0r = l0r * al0 + rs0;
        l1r = l1r * al1 + rs1;

#pragma unroll
        for (int dt = 0; dt < 16; dt++) {
            o[dt][0] *= al0; o[dt][1] *= al0;
            o[dt][2] *= al1; o[dt][3] *= al1;
        }

        uint32_t ph[4][4];
#pragma unroll
        for (int ks = 0; ks < 4; ks++) {
            ph[ks][0] = pack2h(s[2 * ks][0],     s[2 * ks][1]);
            ph[ks][1] = pack2h(s[2 * ks][2],     s[2 * ks][3]);
            ph[ks][2] = pack2h(s[2 * ks + 1][0], s[2 * ks + 1][1]);
            ph[ks][3] = pack2h(s[2 * ks + 1][2], s[2 * ks + 1][3]);
        }

#pragma unroll
        for (int np = 0; np < 8; np++) {
#pragma unroll
            for (int ks = 0; ks < 4; ks++) {
                uint32_t vq[4];
                int key = ks * 16 + (lane & 7) + ((lane >> 3) & 1) * 8;
                int dd = np * 16 + ((lane >> 4) << 3);
                uint32_t lrow = (uint32_t)((dd >> 6) * 64 + key);
                uint32_t off = lrow * 128 + (dd & 63) * 2;
                uint32_t sw = SW128(off);
                LDSM4T(vq, sb + 16384u + sw);
#pragma unroll
                for (int tt = 0; tt < 2; tt++)
                    MMA16816(o[np * 2 + tt], ph[ks], vq[2 * tt], vq[2 * tt + 1]);
            }
        }
        __syncthreads();
    }

    const float inv0 = 1.0f / l0r, inv1 = 1.0f / l1r;
    const size_t ob = ((size_t)(b * S_LEN + q0 + wq)) * D_DIM + h * HDIM;
#pragma unroll
    for (int dt = 0; dt < 16; dt++) {
        const int dd = dt * 8 + tig * 2;
        *(uint32_t*)(O_g + ob + (size_t)gid * D_DIM + dd) =
            pack2h(o[dt][0] * inv0, o[dt][1] * inv0);
        *(uint32_t*)(O_g + ob + (size_t)(gid + 8) * D_DIM + dd) =
            pack2h(o[dt][2] * inv1, o[dt][3] * inv1);
    }
}

// ---------------- launch ------------------------------------------------------
extern "C" void kernel_launch(void* const* d_in, const int* in_sizes, int n_in,
                              void* d_out, int out_size)
{
    const float* x   = (const float*)d_in[0];
    const float* Wq  = (const float*)d_in[1];
    const float* Wkv = (const float*)d_in[2];
    const float* Wk  = (const float*)d_in[3];
    const float* Wv  = (const float*)d_in[4];
    const float* Wo  = (const float*)d_in[5];
    float* out = (float*)d_out;

    __half *X1, *KV1, *Q1, *K1, *V1, *AO1;
    __half *W1, *W2, *WoT;
    cudaGetSymbolAddress((void**)&X1, g_X1);
    cudaGetSymbolAddress((void**)&KV1, g_KV1);
    cudaGetSymbolAddress((void**)&Q1, g_Q1);
    cudaGetSymbolAddress((void**)&K1, g_K1);
    cudaGetSymbolAddress((void**)&V1, g_V1);
    cudaGetSymbolAddress((void**)&AO1, g_AO1);
    cudaGetSymbolAddress((void**)&W1, g_W1);
    cudaGetSymbolAddress((void**)&W2, g_W2);
    cudaGetSymbolAddress((void**)&WoT, g_WoT);

    cudaFuncSetAttribute(mm_kernel,   cudaFuncAttributeMaxDynamicSharedMemorySize, MM_SMEM_BYTES);
    cudaFuncSetAttribute(attn_kernel, cudaFuncAttributeMaxDynamicSharedMemorySize, A_SMEM_BYTES);

    // --- conversions ---
    {
        int n4 = MROWS * D_DIM / 4;
        convert_kernel<<<(n4 + 255) / 256, 256>>>((const float4*)x, (uint32_t*)X1, n4);
    }
    tsplit_all_kernel<<<11264, dim3(32, 8)>>>(Wq, Wkv, Wk, Wv, Wo, W1, W2, WoT);

    // --- [Q | KV] = X @ [Wq | Wkv]  (1-pass; single fp16 out both) ---
    mm_kernel<<<dim3((D_DIM + L_DIM) / 128, MROWS / 128), 256, MM_SMEM_BYTES>>>(
        X1, W1, nullptr,
        Q1, D_DIM, KV1, L_DIM, D_DIM, D_DIM, 2, 2);

    // --- [K | V] = KV @ [Wk | Wv]  (1-pass; single fp16 out) ---
    mm_kernel<<<dim3((2 * D_DIM) / 128, MROWS / 128), 256, MM_SMEM_BYTES>>>(
        KV1, W2, nullptr,
        K1, D_DIM, V1, D_DIM, D_DIM, L_DIM, 2, 2);

    // --- attention (all fp16, 1-pass QK and PV) ---
    attn_kernel<<<dim3(S_LEN / AQT, NHEADS, B_SZ), 256, A_SMEM_BYTES>>>(
        Q1, K1, V1, AO1);

    // --- out = AO @ Wo (1-pass; fp32 out) ---
    mm_kernel<<<dim3(D_DIM / 128, MROWS / 128), 256, MM_SMEM_BYTES>>>(
        AO1, WoT, out,
        nullptr, D_DIM, nullptr, 0, 1 << 30, D_DIM, 0, 0);
}

// round 16
// speedup vs baseline: 1.6881x; 1.0148x over previous
#include <cuda_runtime.h>
#include <cuda_fp16.h>
#include <cstdint>

// ---------------- problem constants ----------------
#define B_SZ   2
#define S_LEN  2048
#define D_DIM  2048
#define L_DIM  512
#define NHEADS 16
#define HDIM   128
#define WIN    128
#define SINK   16
#define MROWS  (B_SZ * S_LEN)   // 4096

// ---------------- PTX helpers (base sm_103 ISA only) ----------------
__device__ __forceinline__ uint32_t smem_to_u32(const void* p) {
    uint32_t a;
    asm("{ .reg .u64 t; cvta.to.shared.u64 t, %1; cvt.u32.u64 %0, t; }" : "=r"(a) : "l"(p));
    return a;
}

#define CP_ASYNC16(saddr, gaddr) \
    asm volatile("cp.async.cg.shared.global [%0], [%1], 16;" :: "r"(saddr), "l"(gaddr) : "memory")
#define CP_COMMIT()  asm volatile("cp.async.commit_group;" ::: "memory")
#define CP_WAIT1()   asm volatile("cp.async.wait_group 1;" ::: "memory")
#define CP_WAIT0()   asm volatile("cp.async.wait_group 0;" ::: "memory")

#define LDSM4(r, addr) \
    asm volatile("ldmatrix.sync.aligned.m8n8.x4.shared.b16 {%0,%1,%2,%3}, [%4];" \
        : "=r"((r)[0]), "=r"((r)[1]), "=r"((r)[2]), "=r"((r)[3]) : "r"(addr))
#define LDSM4T(r, addr) \
    asm volatile("ldmatrix.sync.aligned.m8n8.x4.trans.shared.b16 {%0,%1,%2,%3}, [%4];" \
        : "=r"((r)[0]), "=r"((r)[1]), "=r"((r)[2]), "=r"((r)[3]) : "r"(addr))

// fp16 inputs, fp32 accumulate
#define MMA16816(d, a, b0, b1) \
    asm volatile("mma.sync.aligned.m16n8k16.row.col.f32.f16.f16.f32 " \
        "{%0,%1,%2,%3},{%4,%5,%6,%7},{%8,%9},{%0,%1,%2,%3};" \
        : "+f"((d)[0]), "+f"((d)[1]), "+f"((d)[2]), "+f"((d)[3]) \
        : "r"((a)[0]), "r"((a)[1]), "r"((a)[2]), "r"((a)[3]), "r"(b0), "r"(b1))

__device__ __forceinline__ uint32_t pack2h(float x, float y) {
    __half2 h = __floats2half2_rn(x, y);
    return *(uint32_t*)&h;
}

#define SW128(off) ((off) ^ (((off) >> 3) & 0x70))

// ---------------- scratch (device globals; all single fp16) -------------------
__device__ __align__(256) __half g_X1  [MROWS * D_DIM];
__device__ __align__(256) __half g_KV1 [MROWS * L_DIM];
__device__ __align__(256) __half g_Q1  [MROWS * D_DIM];
__device__ __align__(256) __half g_K1  [MROWS * D_DIM];
__device__ __align__(256) __half g_V1  [MROWS * D_DIM];
__device__ __align__(256) __half g_AO1 [MROWS * D_DIM];
// merged transposed weights (single fp16)
__device__ __align__(256) __half g_W1 [(D_DIM + L_DIM) * D_DIM];
__device__ __align__(256) __half g_W2 [(2 * D_DIM) * L_DIM];
__device__ __align__(256) __half g_WoT[D_DIM * D_DIM];

// ---------------- conversions ----------------
__global__ void convert_kernel(const float4* __restrict__ in,
                               uint32_t* __restrict__ out, int n4)
{
    int i = blockIdx.x * blockDim.x + threadIdx.x;
    if (i >= n4) return;
    float4 v = in[i];
    out[2 * i]     = pack2h(v.x, v.y);
    out[2 * i + 1] = pack2h(v.z, v.w);
}

// One launch converting all 5 weights: src [K,N] fp32 -> dst [N,K] fp16.
__global__ void tsplit_all_kernel(
    const float* __restrict__ Wq, const float* __restrict__ Wkv,
    const float* __restrict__ Wk, const float* __restrict__ Wv,
    const float* __restrict__ Wo,
    __half* __restrict__ W1, __half* __restrict__ W2, __half* __restrict__ WoT)
{
    int t = blockIdx.x;
    const float* src;
    __half* dst;
    int K, N;
    if (t < 4096)      { src = Wq;  dst = W1;                          K = 2048; N = 2048; }
    else if (t < 5120) { src = Wkv; dst = W1 + (size_t)D_DIM * D_DIM;  K = 2048; N = 512;  t -= 4096; }
    else if (t < 6144) { src = Wk;  dst = W2;                          K = 512;  N = 2048; t -= 5120; }
    else if (t < 7168) { src = Wv;  dst = W2 + (size_t)D_DIM * L_DIM;  K = 512;  N = 2048; t -= 6144; }
    else               { src = Wo;  dst = WoT;                         K = 2048; N = 2048; t -= 7168; }

    const int ntx = N >> 5;
    const int nb = (t % ntx) * 32;
    const int kb = (t / ntx) * 32;

    __shared__ float tile[32][33];
    int tx = threadIdx.x, ty = threadIdx.y;
#pragma unroll
    for (int j = 0; j < 32; j += 8)
        tile[ty + j][tx] = src[(size_t)(kb + ty + j) * N + nb + tx];
    __syncthreads();
#pragma unroll
    for (int j = 0; j < 32; j += 8) {
        float v = tile[tx][ty + j];
        dst[(size_t)(nb + ty + j) * K + kb + tx] = __float2half_rn(v);
    }
}

// ---------------- fp16 1-pass HMMA GEMM (64x64 warp tiles) --------------------
// C[M,N] = A[M,K] @ B^T, B stored [N,K] single fp16. fp32 accumulate.
// 128x128 CTA tile, BK=64, 4 warps (2m x 2n, 64x64 each), 128 threads,
// SW128 swizzle, 3-stage cp.async, 96KB smem, occ 2.
#define MM_STAGE 32768u
#define MM_SMEM_BYTES (3 * 32768)

__device__ __forceinline__ void mm_load_chunk(
    uint32_t sb, int ck, int tid,
    const __half* __restrict__ A, const __half* __restrict__ B,
    int m0, int n0, int K)
{
    const int k0 = ck * 64;
#pragma unroll
    for (int it = 0; it < 16; it++) {
        const int arr = it >> 3;                      // 0:A 1:B
        const int u   = ((it & 7) << 7) + tid;        // 0..1023
        const int r   = u >> 3;                       // 0..127
        const int cb  = (u & 7) << 4;                 // byte col in 128B row
        const uint32_t sw = SW128((uint32_t)(r * 128 + cb));
        const __half* base = (arr == 0) ? A : B;
        const int row0 = (arr == 0) ? m0 : n0;
        const char* g = (const char*)(base + (size_t)(row0 + r) * K + k0) + cb;
        CP_ASYNC16(sb + (uint32_t)arr * 16384u + sw, g);
    }
}

__device__ __forceinline__ void mm_body(
    uint32_t smem, int tid,
    const __half* __restrict__ A, const __half* __restrict__ B,
    float* __restrict__ C, __half* __restrict__ Oh,
    int m0, int n0, int nout0, int ncols, int K, int mode)
    // mode: 0 = fp32 to C, 2 = single fp16 to Oh
{
    const int wid  = tid >> 5;
    const int lane = tid & 31;
    const int warp_m = wid & 1;          // 2 x 64 rows
    const int warp_n = wid >> 1;         // 2 x 64 cols

    float d[4][8][4];
#pragma unroll
    for (int mt = 0; mt < 4; mt++)
#pragma unroll
        for (int nt = 0; nt < 8; nt++)
#pragma unroll
            for (int j = 0; j < 4; j++) d[mt][nt][j] = 0.0f;

    const int nch = K / 64;
    mm_load_chunk(smem,            0, tid, A, B, m0, n0, K);
    CP_COMMIT();
    mm_load_chunk(smem + MM_STAGE, 1, tid, A, B, m0, n0, K);
    CP_COMMIT();

    const int a_row  = warp_m * 64 + (lane & 15);
    const int a_kofs = (lane >> 4) << 4;
    const int b_row  = warp_n * 64 + ((lane >> 4) << 3) + (lane & 7);
    const int b_kofs = ((lane >> 3) & 1) << 4;

    for (int i = 0; i < nch; i++) {
        if (i + 1 < nch) CP_WAIT1();
        else             CP_WAIT0();
        __syncthreads();      // all warps past compute(i-1); chunk i visible

        // issue next load AFTER barrier: targets stage (i+2)%3 == (i-1)%3, now free
        if (i + 2 < nch) {
            mm_load_chunk(smem + (uint32_t)((i + 2) % 3) * MM_STAGE, i + 2, tid,
                          A, B, m0, n0, K);
            CP_COMMIT();
        }

        const uint32_t sb = smem + (uint32_t)(i % 3) * MM_STAGE;
#pragma unroll
        for (int ks = 0; ks < 4; ks++) {
            const int kb = ks * 32;
            uint32_t bq[4][4];
#pragma unroll
            for (int np = 0; np < 4; np++) {
                const uint32_t sw = SW128((uint32_t)((b_row + np * 16) * 128 + kb + b_kofs));
                LDSM4(bq[np], sb + 16384u + sw);
            }
#pragma unroll
            for (int mt = 0; mt < 4; mt++) {
                uint32_t aq[4];
                const uint32_t sw = SW128((uint32_t)((a_row + mt * 16) * 128 + kb + a_kofs));
                LDSM4(aq, sb + sw);
#pragma unroll
                for (int nt = 0; nt < 8; nt++) {
                    const int np = nt >> 1, h = (nt & 1) << 1;
                    MMA16816(d[mt][nt], aq, bq[np][h], bq[np][h + 1]);
                }
            }
        }
    }

    // epilogue
    const int gid = lane >> 2, tig = lane & 3;
    const int mbase = m0 + warp_m * 64 + gid;
    const int nbase = nout0 + warp_n * 64 + tig * 2;
    if (mode == 0) {
#pragma unroll
        for (int mt = 0; mt < 4; mt++)
#pragma unroll
            for (int nt = 0; nt < 8; nt++) {
                const int m = mbase + mt * 16;
                const int n = nbase + nt * 8;
                *(float2*)(C + (size_t)m * ncols + n)       = make_float2(d[mt][nt][0], d[mt][nt][1]);
                *(float2*)(C + (size_t)(m + 8) * ncols + n) = make_float2(d[mt][nt][2], d[mt][nt][3]);
            }
    } else {
#pragma unroll
        for (int mt = 0; mt < 4; mt++)
#pragma unroll
            for (int nt = 0; nt < 8; nt++) {
#pragma unroll
                for (int half = 0; half < 2; half++) {
                    const int m = mbase + mt * 16 + half * 8;
                    const int n = nbase + nt * 8;
                    *(uint32_t*)(Oh + (size_t)m * ncols + n) =
                        pack2h(d[mt][nt][half * 2], d[mt][nt][half * 2 + 1]);
                }
            }
    }
}

__global__ __launch_bounds__(128, 2)
void mm_kernel(const __half* __restrict__ A,
               const __half* __restrict__ B,
               float* __restrict__ C,
               __half* __restrict__ O_a, int ncols_a,
               __half* __restrict__ O_b, int ncols_b,
               int nsplit, int K, int mode_a, int mode_b)
{
    extern __shared__ __align__(1024) char dsm[];
    const uint32_t smem = smem_to_u32(dsm);
    const int tid = threadIdx.x;
    const int m0 = blockIdx.y * 128, n0 = blockIdx.x * 128;
    const bool second = (n0 >= nsplit);

    if (!second) {
        mm_body(smem, tid, A, B, C, O_a, m0, n0, n0, ncols_a, K, mode_a);
    } else {
        mm_body(smem, tid, A, B, C, O_b, m0, n0, n0 - nsplit, ncols_b, K, mode_b);
    }
}

// ---------------- fp16 1-pass flash attention (sliding window + sink) ----------
#define AQT 128
#define AKT 64
#define A_STAGE_OFF   32768u           // Q 32K
#define A_STAGE_BYTES 32768u           // K 16K + V 16K
#define A_SMEM_BYTES  (32768 + 2 * 32768)

__global__ __launch_bounds__(256, 1) void attn_kernel(
    const __half* __restrict__ Q_g,
    const __half* __restrict__ K_g,  const __half* __restrict__ V_g,
    __half* __restrict__ O_g)
{
    extern __shared__ __align__(1024) char dsm[];
    const uint32_t smem = smem_to_u32(dsm);
    const int tid = threadIdx.x, wid = tid >> 5, lane = tid & 31;
    const int b = blockIdx.z, h = blockIdx.y;
    const int q0 = blockIdx.x * AQT;
    const int gid = lane >> 2, tig = lane & 3;
    const int wq = wid * 16;
    const float scale = 0.08838834764831845f;

    {
        const size_t qg = ((size_t)(b * S_LEN + q0)) * D_DIM + h * HDIM;
#pragma unroll
        for (int it = 0; it < 8; it++) {
            int ch = tid + it * 256;
            int row = ch >> 4, dblk = ch & 15;
            uint32_t lrow = (uint32_t)((dblk >> 3) * 128 + row);
            uint32_t off = lrow * 128 + (dblk & 7) * 16;
            uint32_t sw = SW128(off);
            size_t g = qg + (size_t)row * D_DIM + dblk * 8;
            CP_ASYNC16(smem + sw, (const char*)(Q_g + g));
        }
        CP_COMMIT();
    }

    const int ws = q0 - WIN + 1;
    const int tstart = (ws >= 64) ? (ws >> 6) : 1;
    const int tend = (q0 + AQT - 1) >> 6;
    const int cnt = 2 + (tend - tstart);

#define TILE_OF(j) ((j) == 0 ? 0 : (tstart + (j) - 1))
#define LOAD_KV(j) do { \
        int kb_ = TILE_OF(j) * AKT; \
        uint32_t sb_ = smem + A_STAGE_OFF + (uint32_t)((j) & 1) * A_STAGE_BYTES; \
        size_t gb_ = ((size_t)(b * S_LEN + kb_)) * D_DIM + h * HDIM; \
        _Pragma("unroll") \
        for (int it_ = 0; it_ < 4; it_++) { \
            int ch_ = tid + it_ * 256; \
            int row_ = ch_ >> 4, dblk_ = ch_ & 15; \
            uint32_t lrow_ = (uint32_t)((dblk_ >> 3) * 64 + row_); \
            uint32_t off_ = lrow_ * 128 + (dblk_ & 7) * 16; \
            uint32_t sw_ = SW128(off_); \
            size_t g_ = gb_ + (size_t)row_ * D_DIM + dblk_ * 8; \
            CP_ASYNC16(sb_ + sw_,           (const char*)(K_g + g_)); \
            CP_ASYNC16(sb_ + 16384u + sw_,  (const char*)(V_g + g_)); \
        } \
        CP_COMMIT(); \
    } while (0)

    LOAD_KV(0);

    float o[16][4];
#pragma unroll
    for (int dt = 0; dt < 16; dt++)
#pragma unroll
        for (int j = 0; j < 4; j++) o[dt][j] = 0.0f;
    float m0r = -1e30f, m1r = -1e30f, l0r = 0.0f, l1r = 0.0f;

    for (int j = 0; j < cnt; j++) {
        if (j + 1 < cnt) { LOAD_KV(j + 1); CP_WAIT1(); }
        else             { CP_WAIT0(); }
        __syncthreads();

        const uint32_t sb = smem + A_STAGE_OFF + (uint32_t)(j & 1) * A_STAGE_BYTES;
        const int kb = TILE_OF(j) * AKT;

        float s[8][4];
#pragma unroll
        for (int nt = 0; nt < 8; nt++)
#pragma unroll
            for (int jj = 0; jj < 4; jj++) s[nt][jj] = 0.0f;

#pragma unroll
        for (int ks = 0; ks < 8; ks++) {
            uint32_t aq[4];
            {
                int dd = ks * 16 + ((lane >> 4) << 3);
                int row = wq + (lane & 15);
                uint32_t lrow = (uint32_t)((dd >> 6) * 128 + row);
                uint32_t off = lrow * 128 + (dd & 63) * 2;
                uint32_t sw = SW128(off);
                LDSM4(aq, smem + sw);
            }
#pragma unroll
            for (int np = 0; np < 4; np++) {
                uint32_t bq[4];
                int key = np * 16 + ((lane >> 4) << 3) + (lane & 7);
                int dd = ks * 16 + ((lane >> 3) & 1) * 8;
                uint32_t lrow = (uint32_t)((dd >> 6) * 64 + key);
                uint32_t off = lrow * 128 + (dd & 63) * 2;
                uint32_t sw = SW128(off);
                LDSM4(bq, sb + sw);
#pragma unroll
                for (int tt = 0; tt < 2; tt++)
                    MMA16816(s[np * 2 + tt], aq, bq[2 * tt], bq[2 * tt + 1]);
            }
        }

#pragma unroll
        for (int nt = 0; nt < 8; nt++) {
            const int kc = kb + nt * 8 + tig * 2;
#pragma unroll
            for (int jj = 0; jj < 4; jj++) {
                const int q = q0 + wq + gid + ((jj >> 1) << 3);
                const int k = kc + (jj & 1);
                const bool valid = (k <= q) && ((q - k < WIN) || (k < SINK));
                s[nt][jj] = valid ? s[nt][jj] * scale : -1e30f;
            }
        }

        float tm0 = -1e30f, tm1 = -1e30f;
#pragma unroll
        for (int nt = 0; nt < 8; nt++) {
            tm0 = fmaxf(tm0, fmaxf(s[nt][0], s[nt][1]));
            tm1 = fmaxf(tm1, fmaxf(s[nt][2], s[nt][3]));
        }
        tm0 = fmaxf(tm0, __shfl_xor_sync(0xffffffffu, tm0, 1));
        tm0 = fmaxf(tm0, __shfl_xor_sync(0xffffffffu, tm0, 2));
        tm1 = fmaxf(tm1, __shfl_xor_sync(0xffffffffu, tm1, 1));
        tm1 = fmaxf(tm1, __shfl_xor_sync(0xffffffffu, tm1, 2));
        const float m0n = fmaxf(m0r, tm0), m1n = fmaxf(m1r, tm1);
        const float al0 = __expf(m0r - m0n), al1 = __expf(m1r - m1n);
        m0r = m0n; m1r = m1n;

        float rs0 = 0.0f, rs1 = 0.0f;
#pragma unroll
        for (int nt = 0; nt < 8; nt++) {
            float p0 = __expf(s[nt][0] - m0n);
            float p1 = __expf(s[nt][1] - m0n);
            float p2 = __expf(s[nt][2] - m1n);
            float p3 = __expf(s[nt][3] - m1n);
            s[nt][0] = p0; s[nt][1] = p1; s[nt][2] = p2; s[nt][3] = p3;
            rs0 += p0 + p1; rs1 += p2 + p3;
        }
        rs0 += __shfl_xor_sync(0xffffffffu, rs0, 1);
        rs0 += __shfl_xor_sync(0xffffffffu, rs0, 2);
        rs1 += __shfl_xor_sync(0xffffffffu, rs1, 1);
        rs1 += __shfl_xor_sync(0xffffffffu, rs1, 2);
        l0r = l0r * al0 + rs0;
        l1r = l1r * al1 + rs1;

#pragma unroll
        for (int dt = 0; dt < 16; dt++) {
            o[dt][0] *= al0; o[dt][1] *= al0;
            o[dt][2] *= al1; o[dt][3] *= al1;
        }

        uint32_t ph[4][4];
#pragma unroll
        for (int ks = 0; ks < 4; ks++) {
            ph[ks][0] = pack2h(s[2 * ks][0],     s[2 * ks][1]);
            ph[ks][1] = pack2h(s[2 * ks][2],     s[2 * ks][3]);
            ph[ks][2] = pack2h(s[2 * ks + 1][0], s[2 * ks + 1][1]);
            ph[ks][3] = pack2h(s[2 * ks + 1][2], s[2 * ks + 1][3]);
        }

#pragma unroll
        for (int np = 0; np < 8; np++) {
#pragma unroll
            for (int ks = 0; ks < 4; ks++) {
                uint32_t vq[4];
                int key = ks * 16 + (lane & 7) + ((lane >> 3) & 1) * 8;
                int dd = np * 16 + ((lane >> 4) << 3);
                uint32_t lrow = (uint32_t)((dd >> 6) * 64 + key);
                uint32_t off = lrow * 128 + (dd & 63) * 2;
                uint32_t sw = SW128(off);
                LDSM4T(vq, sb + 16384u + sw);
#pragma unroll
                for (int tt = 0; tt < 2; tt++)
                    MMA16816(o[np * 2 + tt], ph[ks], vq[2 * tt], vq[2 * tt + 1]);
            }
        }
        __syncthreads();
    }

    const float inv0 = 1.0f / l0r, inv1 = 1.0f / l1r;
    const size_t ob = ((size_t)(b * S_LEN + q0 + wq)) * D_DIM + h * HDIM;
#pragma unroll
    for (int dt = 0; dt < 16; dt++) {
        const int dd = dt * 8 + tig * 2;
        *(uint32_t*)(O_g + ob + (size_t)gid * D_DIM + dd) =
            pack2h(o[dt][0] * inv0, o[dt][1] * inv0);
        *(uint32_t*)(O_g + ob + (size_t)(gid + 8) * D_DIM + dd) =
            pack2h(o[dt][2] * inv1, o[dt][3] * inv1);
    }
}

// ---------------- launch ------------------------------------------------------
extern "C" void kernel_launch(void* const* d_in, const int* in_sizes, int n_in,
                              void* d_out, int out_size)
{
    const float* x   = (const float*)d_in[0];
    const float* Wq  = (const float*)d_in[1];
    const float* Wkv = (const float*)d_in[2];
    const float* Wk  = (const float*)d_in[3];
    const float* Wv  = (const float*)d_in[4];
    const float* Wo  = (const float*)d_in[5];
    float* out = (float*)d_out;

    __half *X1, *KV1, *Q1, *K1, *V1, *AO1;
    __half *W1, *W2, *WoT;
    cudaGetSymbolAddress((void**)&X1, g_X1);
    cudaGetSymbolAddress((void**)&KV1, g_KV1);
    cudaGetSymbolAddress((void**)&Q1, g_Q1);
    cudaGetSymbolAddress((void**)&K1, g_K1);
    cudaGetSymbolAddress((void**)&V1, g_V1);
    cudaGetSymbolAddress((void**)&AO1, g_AO1);
    cudaGetSymbolAddress((void**)&W1, g_W1);
    cudaGetSymbolAddress((void**)&W2, g_W2);
    cudaGetSymbolAddress((void**)&WoT, g_WoT);

    cudaFuncSetAttribute(mm_kernel,   cudaFuncAttributeMaxDynamicSharedMemorySize, MM_SMEM_BYTES);
    cudaFuncSetAttribute(attn_kernel, cudaFuncAttributeMaxDynamicSharedMemorySize, A_SMEM_BYTES);

    // --- conversions ---
    {
        int n4 = MROWS * D_DIM / 4;
        convert_kernel<<<(n4 + 255) / 256, 256>>>((const float4*)x, (uint32_t*)X1, n4);
    }
    tsplit_all_kernel<<<11264, dim3(32, 8)>>>(Wq, Wkv, Wk, Wv, Wo, W1, W2, WoT);

    // --- [Q | KV] = X @ [Wq | Wkv]  (1-pass; single fp16 out both) ---
    mm_kernel<<<dim3((D_DIM + L_DIM) / 128, MROWS / 128), 128, MM_SMEM_BYTES>>>(
        X1, W1, nullptr,
        Q1, D_DIM, KV1, L_DIM, D_DIM, D_DIM, 2, 2);

    // --- [K | V] = KV @ [Wk | Wv]  (1-pass; single fp16 out) ---
    mm_kernel<<<dim3((2 * D_DIM) / 128, MROWS / 128), 128, MM_SMEM_BYTES>>>(
        KV1, W2, nullptr,
        K1, D_DIM, V1, D_DIM, D_DIM, L_DIM, 2, 2);

    // --- attention (all fp16, 1-pass QK and PV) ---
    attn_kernel<<<dim3(S_LEN / AQT, NHEADS, B_SZ), 256, A_SMEM_BYTES>>>(
        Q1, K1, V1, AO1);

    // --- out = AO @ Wo (1-pass; fp32 out) ---
    mm_kernel<<<dim3(D_DIM / 128, MROWS / 128), 128, MM_SMEM_BYTES>>>(
        AO1, WoT, out,
        nullptr, D_DIM, nullptr, 0, 1 << 30, D_DIM, 0, 0);
}